// round 1
// baseline (speedup 1.0000x reference)
#include <cuda_runtime.h>
#include <math.h>
#include <stdint.h>

// ---------------- problem constants ----------------
#define NOBJ 256
#define NHUM 64
#define EDIM 1024
#define NPAIR 16384      // 64*256 (full grid incl diagonal)
#define NKEEP 16320
#define OUTC 4213        // 4*1024 + 117
#define NCLS 117

// ---------------- scratch (static device memory; no allocs) ----------------
__device__ float g_enc1[NOBJ*EDIM];
__device__ float g_encA[NOBJ*EDIM];
__device__ float g_encB[NOBJ*EDIM];
__device__ float g_hA[NHUM*EDIM];
__device__ float g_hB[NHUM*EDIM];
__device__ float g_nssa[NOBJ*EDIM];
__device__ float g_Ah[NHUM*2048];
__device__ float g_Ao[NOBJ*2048];
__device__ float g_hdn2[(size_t)NPAIR*EDIM];   // 64 MB
__device__ float g_adj[NPAIR];
__device__ float g_obj[NOBJ*EDIM];
__device__ float g_hum[NHUM*EDIM];
__device__ float g_aggo[NHUM*EDIM];
__device__ float g_aggh[NOBJ*EDIM];
__device__ int   g_mask_mode;   // 0=uint8(bool), 1=int32, 2=float32

// ---------------- generic fp32 tiled GEMM: C = act(A@B [+bias] [+C]) ----------------
// A: MxK row-major, B: KxN row-major. M%64==0, N%64==0, K%16==0.
#define FLAG_ACC  1
#define FLAG_RELU 2

__global__ void gemm64(const float* __restrict__ A, const float* __restrict__ B,
                       const float* __restrict__ bias, float* __restrict__ C,
                       int M, int N, int K, int flags)
{
    __shared__ float As[16][64];
    __shared__ float Bs[16][64];
    const int row0 = blockIdx.y * 64;
    const int col0 = blockIdx.x * 64;
    const int t = threadIdx.x;           // 0..255
    const int ty = t >> 4, tx = t & 15;

    float acc[4][4] = {};

    for (int k0 = 0; k0 < K; k0 += 16) {
        #pragma unroll
        for (int i = 0; i < 4; i++) {
            int idx = t + i * 256;
            int r = idx >> 4, c = idx & 15;
            As[c][r] = A[(size_t)(row0 + r) * K + (k0 + c)];
        }
        #pragma unroll
        for (int i = 0; i < 4; i++) {
            int idx = t + i * 256;
            int r = idx >> 6, c = idx & 63;
            Bs[r][c] = B[(size_t)(k0 + r) * N + (col0 + c)];
        }
        __syncthreads();
        #pragma unroll
        for (int k = 0; k < 16; k++) {
            float a[4], b[4];
            #pragma unroll
            for (int i = 0; i < 4; i++) a[i] = As[k][ty * 4 + i];
            #pragma unroll
            for (int j = 0; j < 4; j++) b[j] = Bs[k][tx * 4 + j];
            #pragma unroll
            for (int i = 0; i < 4; i++)
                #pragma unroll
                for (int j = 0; j < 4; j++)
                    acc[i][j] += a[i] * b[j];
        }
        __syncthreads();
    }

    #pragma unroll
    for (int i = 0; i < 4; i++) {
        int row = row0 + ty * 4 + i;
        #pragma unroll
        for (int j = 0; j < 4; j++) {
            int col = col0 + tx * 4 + j;
            size_t idx = (size_t)row * N + col;
            float v = acc[i][j];
            if (bias) v += bias[col];
            if (flags & FLAG_ACC) v += C[idx];
            if (flags & FLAG_RELU) v = fmaxf(v, 0.f);
            C[idx] = v;
        }
    }
}

// ---------------- fused pair GEMM: hdn2 = relu( relu(Ah[h]+Ao[n]) @ W_a2 + b_a2 ) ----
// M=16384 (p = h*256+n), K=2048, N=1024
__global__ void pairgemm(const float* __restrict__ Ah, const float* __restrict__ Ao,
                         const float* __restrict__ B, const float* __restrict__ bias,
                         float* __restrict__ C)
{
    __shared__ float As[16][64];
    __shared__ float Bs[16][64];
    const int row0 = blockIdx.y * 64;
    const int col0 = blockIdx.x * 64;
    const int t = threadIdx.x;
    const int ty = t >> 4, tx = t & 15;

    float acc[4][4] = {};

    for (int k0 = 0; k0 < 2048; k0 += 16) {
        #pragma unroll
        for (int i = 0; i < 4; i++) {
            int idx = t + i * 256;
            int r = idx >> 4, c = idx & 15;
            int grow = row0 + r;
            int h = grow >> 8, n = grow & 255;
            As[c][r] = fmaxf(Ah[h * 2048 + k0 + c] + Ao[n * 2048 + k0 + c], 0.f);
        }
        #pragma unroll
        for (int i = 0; i < 4; i++) {
            int idx = t + i * 256;
            int r = idx >> 6, c = idx & 63;
            Bs[r][c] = B[(size_t)(k0 + r) * 1024 + (col0 + c)];
        }
        __syncthreads();
        #pragma unroll
        for (int k = 0; k < 16; k++) {
            float a[4], b[4];
            #pragma unroll
            for (int i = 0; i < 4; i++) a[i] = As[k][ty * 4 + i];
            #pragma unroll
            for (int j = 0; j < 4; j++) b[j] = Bs[k][tx * 4 + j];
            #pragma unroll
            for (int i = 0; i < 4; i++)
                #pragma unroll
                for (int j = 0; j < 4; j++)
                    acc[i][j] += a[i] * b[j];
        }
        __syncthreads();
    }

    #pragma unroll
    for (int i = 0; i < 4; i++) {
        int row = row0 + ty * 4 + i;
        #pragma unroll
        for (int j = 0; j < 4; j++) {
            int col = col0 + tx * 4 + j;
            float v = fmaxf(acc[i][j] + bias[col], 0.f);
            C[(size_t)row * 1024 + col] = v;
        }
    }
}

// ---------------- adj = sigmoid(hdn2 @ W_a3 + b_a3), one warp per pair --------------
__global__ void adj_k(const float* __restrict__ hdn2, const float* __restrict__ w3,
                      const float* __restrict__ b3, float* __restrict__ adj)
{
    int p = blockIdx.x * 8 + (threadIdx.x >> 5);
    int lane = threadIdx.x & 31;
    const float* row = hdn2 + (size_t)p * 1024;
    float s = 0.f;
    #pragma unroll 4
    for (int j = lane; j < 1024; j += 32) s += row[j] * w3[j];
    #pragma unroll
    for (int o = 16; o > 0; o >>= 1) s += __shfl_xor_sync(0xffffffffu, s, o);
    if (lane == 0) adj[p] = 1.f / (1.f + expf(-(s + b3[0])));
}

// ---------------- agg_o[h,e] = hs_sa[h,e]*sum_n adj*om - sum_n adj*om*ns_sa ---------
__global__ void aggo_k(const float* __restrict__ adj, const float* __restrict__ obj,
                       const float* __restrict__ nssa, float* __restrict__ out)
{
    int h = blockIdx.y;
    int e = blockIdx.x * 128 + threadIdx.x;
    __shared__ float sa[256];
    for (int i = threadIdx.x; i < 256; i += 128) sa[i] = adj[h * 256 + i];
    __syncthreads();
    float a1 = 0.f, a2 = 0.f;
    #pragma unroll 4
    for (int n = 0; n < 256; n++) {
        float a = sa[n];
        float om = obj[n * 1024 + e];
        float ns = nssa[n * 1024 + e];
        a1 += a * om;
        a2 += a * om * ns;
    }
    out[h * 1024 + e] = nssa[h * 1024 + e] * a1 - a2;
}

// ---------------- agg_h[n,e] = ns_sa[n,e]*sum_h adj*hm - sum_h adj*hm*hs_sa ---------
__global__ void aggh_k(const float* __restrict__ adj, const float* __restrict__ hum,
                       const float* __restrict__ nssa, float* __restrict__ out)
{
    int n = blockIdx.y;
    int e = blockIdx.x * 128 + threadIdx.x;
    __shared__ float sa[64];
    if (threadIdx.x < 64) sa[threadIdx.x] = adj[threadIdx.x * 256 + n];
    __syncthreads();
    float a1 = 0.f, a2 = 0.f;
    #pragma unroll 4
    for (int h = 0; h < 64; h++) {
        float a = sa[h];
        float hm = hum[h * 1024 + e];
        float hs = nssa[h * 1024 + e];
        a1 += a * hm;
        a2 += a * hm * hs;
    }
    out[n * 1024 + e] = nssa[n * 1024 + e] * a1 - a2;
}

// ---------------- helpers ----------------
__global__ void copy_k(float* __restrict__ dst, const float* __restrict__ src, int n)
{
    int i = blockIdx.x * blockDim.x + threadIdx.x;
    if (i < n) dst[i] = src[i];
}

// detect class_mask dtype from its first 9360 bytes (always safe to read)
__global__ void detect_k(const unsigned char* __restrict__ cm)
{
    __shared__ int s_f, s_nz;
    if (threadIdx.x == 0) { s_f = 0; s_nz = 0; }
    __syncthreads();
    int lf = 0, lnz = 0;
    for (int i = threadIdx.x; i < 9360; i += blockDim.x) {
        unsigned char b = cm[i];
        int m4 = i & 3;
        if (m4 == 3 && b == 0x3F) lf = 1;
        if (m4 != 0 && b != 0) lnz = 1;
    }
    if (lf) atomicOr(&s_f, 1);
    if (lnz) atomicOr(&s_nz, 1);
    __syncthreads();
    if (threadIdx.x == 0) {
        g_mask_mode = s_f ? 2 : (s_nz ? 0 : 1);
    }
}

__device__ __forceinline__ float lisf(float x)
{
    return 8.3f / (1.f + expf(12.f - 10.f * x));
}

// ---------------- final gather: one block per kept pair row ----------------
__global__ void out_k(const float* __restrict__ hfin, const float* __restrict__ efin,
                      const float* __restrict__ nsp, const float* __restrict__ adj,
                      const float* __restrict__ scores, const int* __restrict__ labels,
                      const void* __restrict__ cmask, float* __restrict__ out)
{
    int p = blockIdx.x;                 // 0..16319
    int x = p / 255;
    int r = p % 255;
    int y = (r < x) ? r : r + 1;

    float scale = adj[x * 256 + y] * lisf(scores[x]) * lisf(scores[y]);
    int lab = labels[y];
    int mode = g_mask_mode;

    const float* hx = hfin + x * 1024;
    const float* sx = nsp + x * 1024;
    const float* ey = efin + y * 1024;
    const float* ny = nsp + y * 1024;
    float* o = out + (size_t)p * OUTC;

    for (int c = threadIdx.x; c < OUTC; c += blockDim.x) {
        float v;
        if (c < 1024)       v = hx[c];
        else if (c < 2048)  v = sx[c - 1024];
        else if (c < 3072)  v = ey[c - 2048];
        else if (c < 4096)  v = ny[c - 3072];
        else {
            int j = c - 4096;
            float m;
            if (mode == 0)      m = ((const unsigned char*)cmask)[lab * NCLS + j] ? 1.f : 0.f;
            else if (mode == 1) m = ((const int*)cmask)[lab * NCLS + j] ? 1.f : 0.f;
            else                m = ((const float*)cmask)[lab * NCLS + j];
            v = scale * m;
        }
        o[c] = v;
    }
}

// ---------------- host ----------------
static inline void launch_gemm(const float* A, const float* B, const float* bias,
                               float* C, int M, int N, int K, int flags)
{
    dim3 grid(N / 64, M / 64);
    gemm64<<<grid, 256>>>(A, B, bias, C, M, N, K, flags);
}

extern "C" void kernel_launch(void* const* d_in, const int* in_sizes, int n_in,
                              void* d_out, int out_size)
{
    // ---- bind inputs by element-count pattern (robust to ordering) ----
    const float *box = 0, *nsp = 0, *scores = 0;
    const int *labels = 0;
    const void *cmask = 0;
    const float *W_bh1 = 0, *b_bh1 = 0, *W_bh2 = 0, *b_bh2 = 0, *W_sa = 0;
    const float *W_a1 = 0, *b_a1 = 0, *W_a2 = 0, *b_a2 = 0, *W_a3 = 0, *b_a3 = 0;
    const float *W_hm = 0, *b_hm = 0, *W_om = 0, *b_om = 0, *W_hu = 0, *W_ou = 0;

    int c256 = 0, c1k = 0, c1m = 0, c2m = 0;
    for (int i = 0; i < n_in; i++) {
        const void* p = d_in[i];
        switch (in_sizes[i]) {
            case 3211264:  box = (const float*)p; break;
            case 262144:   nsp = (const float*)p; break;
            case 256:      if (c256++ == 0) scores = (const float*)p; else labels = (const int*)p; break;
            case 9360:     cmask = p; break;
            case 12845056: W_bh1 = (const float*)p; break;
            case 1024:
                switch (c1k++) {
                    case 0: b_bh1 = (const float*)p; break;
                    case 1: b_bh2 = (const float*)p; break;
                    case 2: b_a2  = (const float*)p; break;
                    case 3: W_a3  = (const float*)p; break;
                    case 4: b_hm  = (const float*)p; break;
                    case 5: b_om  = (const float*)p; break;
                } break;
            case 1048576:
                switch (c1m++) {
                    case 0: W_bh2 = (const float*)p; break;
                    case 1: W_sa  = (const float*)p; break;
                    case 2: W_hm  = (const float*)p; break;
                    case 3: W_om  = (const float*)p; break;
                } break;
            case 8388608:  W_a1 = (const float*)p; break;
            case 2048:     b_a1 = (const float*)p; break;
            case 2097152:
                switch (c2m++) {
                    case 0: W_a2 = (const float*)p; break;
                    case 1: W_hu = (const float*)p; break;
                    case 2: W_ou = (const float*)p; break;
                } break;
            case 1:        b_a3 = (const float*)p; break;
            default: break;
        }
    }

    // ---- scratch pointers ----
    float *enc1, *encA, *encB, *hA, *hB, *nssa, *Ah, *Ao, *hdn2, *adj, *obj, *hum, *aggo, *aggh;
    cudaGetSymbolAddress((void**)&enc1, g_enc1);
    cudaGetSymbolAddress((void**)&encA, g_encA);
    cudaGetSymbolAddress((void**)&encB, g_encB);
    cudaGetSymbolAddress((void**)&hA,   g_hA);
    cudaGetSymbolAddress((void**)&hB,   g_hB);
    cudaGetSymbolAddress((void**)&nssa, g_nssa);
    cudaGetSymbolAddress((void**)&Ah,   g_Ah);
    cudaGetSymbolAddress((void**)&Ao,   g_Ao);
    cudaGetSymbolAddress((void**)&hdn2, g_hdn2);
    cudaGetSymbolAddress((void**)&adj,  g_adj);
    cudaGetSymbolAddress((void**)&obj,  g_obj);
    cudaGetSymbolAddress((void**)&hum,  g_hum);
    cudaGetSymbolAddress((void**)&aggo, g_aggo);
    cudaGetSymbolAddress((void**)&aggh, g_aggh);

    // ---- encoder ----
    launch_gemm(box,  W_bh1, b_bh1, enc1, NOBJ, EDIM, 12544, FLAG_RELU);
    launch_gemm(enc1, W_bh2, b_bh2, encA, NOBJ, EDIM, 1024,  FLAG_RELU);
    launch_gemm(nsp,  W_sa,  0,     nssa, NOBJ, EDIM, 1024,  0);
    copy_k<<<(NHUM * EDIM + 255) / 256, 256>>>(hA, encA, NHUM * EDIM);

    float* enc_in = encA;  float* enc_out = encB;
    float* h_in = hA;      float* h_out = hB;

    for (int it = 0; it < 2; it++) {
        // A_h = [h_enc | h_sp] @ W_a1[:2048] + b_a1   (h_sp = nsp rows 0..63)
        launch_gemm(h_in, W_a1,                0,    Ah, NHUM, 2048, 1024, 0);
        launch_gemm(nsp,  W_a1 + 1024 * 2048,  b_a1, Ah, NHUM, 2048, 1024, FLAG_ACC);
        // A_o = [enc | node_spatial] @ W_a1[2048:]
        launch_gemm(enc_in, W_a1 + 2048 * 2048, 0, Ao, NOBJ, 2048, 1024, 0);
        launch_gemm(nsp,    W_a1 + 3072 * 2048, 0, Ao, NOBJ, 2048, 1024, FLAG_ACC);

        // hdn2 = relu( relu(Ah[h]+Ao[n]) @ W_a2 + b_a2 )
        pairgemm<<<dim3(16, 256), 256>>>(Ah, Ao, W_a2, b_a2, hdn2);

        // adj = sigmoid(hdn2 @ W_a3 + b_a3)
        adj_k<<<NPAIR / 8, 256>>>(hdn2, W_a3, b_a3, adj);

        // obj_msg, agg_o
        launch_gemm(enc_in, W_om, b_om, obj, NOBJ, EDIM, 1024, FLAG_RELU);
        aggo_k<<<dim3(8, NHUM), 128>>>(adj, obj, nssa, aggo);

        // h_enc = [h_enc | agg_o] @ W_hu
        launch_gemm(h_in, W_hu,               0, h_out, NHUM, EDIM, 1024, 0);
        launch_gemm(aggo, W_hu + 1024 * 1024, 0, h_out, NHUM, EDIM, 1024, FLAG_ACC);

        // hum_msg, agg_h
        launch_gemm(h_out, W_hm, b_hm, hum, NHUM, EDIM, 1024, FLAG_RELU);
        aggh_k<<<dim3(8, NOBJ), 128>>>(adj, hum, nssa, aggh);

        // enc = [enc | agg_h] @ W_ou
        launch_gemm(enc_in, W_ou,               0, enc_out, NOBJ, EDIM, 1024, 0);
        launch_gemm(aggh,   W_ou + 1024 * 1024, 0, enc_out, NOBJ, EDIM, 1024, FLAG_ACC);

        // ping-pong
        float* t;
        t = enc_in; enc_in = enc_out; enc_out = t;
        t = h_in;   h_in = h_out;     h_out = t;
    }

    // ---- final gather ----
    detect_k<<<1, 256>>>((const unsigned char*)cmask);
    out_k<<<NKEEP, 128>>>(h_in, enc_in, nsp, adj, scores, labels, cmask, (float*)d_out);
}

// round 2
// speedup vs baseline: 1.0038x; 1.0038x over previous
#include <cuda_runtime.h>
#include <math.h>
#include <stdint.h>

// ---------------- problem constants ----------------
#define NOBJ 256
#define NHUM 64
#define EDIM 1024
#define NPAIR 16384      // 64*256 (full grid incl diagonal)
#define NKEEP 16320
#define OUTC 4213        // 4*1024 + 117
#define NCLS 117

// ---------------- scratch (static device memory; no allocs) ----------------
__device__ float g_enc1[NOBJ*EDIM];
__device__ float g_encA[NOBJ*EDIM];
__device__ float g_encB[NOBJ*EDIM];
__device__ float g_hA[NHUM*EDIM];
__device__ float g_hB[NHUM*EDIM];
__device__ float g_nssa[NOBJ*EDIM];
__device__ float g_Ah[NHUM*2048];
__device__ float g_Ao[NOBJ*2048];
__device__ float g_hdn2[(size_t)NPAIR*EDIM];   // 64 MB
__device__ float g_adj[NPAIR];
__device__ float g_obj[NOBJ*EDIM];
__device__ float g_hum[NHUM*EDIM];
__device__ float g_aggo[NHUM*EDIM];
__device__ float g_aggh[NOBJ*EDIM];
__device__ int   g_mask_mode;   // 0=uint8(bool), 1=int32, 2=float32

// ---------------- generic fp32 tiled GEMM: C = act(A@B [+bias] [+C]) ----------------
// A: MxK row-major, B: KxN row-major. M%64==0, N%64==0, K%16==0.
#define FLAG_ACC  1
#define FLAG_RELU 2

__global__ void gemm64(const float* __restrict__ A, const float* __restrict__ B,
                       const float* __restrict__ bias, float* __restrict__ C,
                       int M, int N, int K, int flags)
{
    __shared__ float As[16][64];
    __shared__ float Bs[16][64];
    const int row0 = blockIdx.y * 64;
    const int col0 = blockIdx.x * 64;
    const int t = threadIdx.x;           // 0..255
    const int ty = t >> 4, tx = t & 15;

    float acc[4][4] = {};

    for (int k0 = 0; k0 < K; k0 += 16) {
        #pragma unroll
        for (int i = 0; i < 4; i++) {
            int idx = t + i * 256;
            int r = idx >> 4, c = idx & 15;
            As[c][r] = A[(size_t)(row0 + r) * K + (k0 + c)];
        }
        #pragma unroll
        for (int i = 0; i < 4; i++) {
            int idx = t + i * 256;
            int r = idx >> 6, c = idx & 63;
            Bs[r][c] = B[(size_t)(k0 + r) * N + (col0 + c)];
        }
        __syncthreads();
        #pragma unroll
        for (int k = 0; k < 16; k++) {
            float a[4], b[4];
            #pragma unroll
            for (int i = 0; i < 4; i++) a[i] = As[k][ty * 4 + i];
            #pragma unroll
            for (int j = 0; j < 4; j++) b[j] = Bs[k][tx * 4 + j];
            #pragma unroll
            for (int i = 0; i < 4; i++)
                #pragma unroll
                for (int j = 0; j < 4; j++)
                    acc[i][j] += a[i] * b[j];
        }
        __syncthreads();
    }

    #pragma unroll
    for (int i = 0; i < 4; i++) {
        int row = row0 + ty * 4 + i;
        #pragma unroll
        for (int j = 0; j < 4; j++) {
            int col = col0 + tx * 4 + j;
            size_t idx = (size_t)row * N + col;
            float v = acc[i][j];
            if (bias) v += bias[col];
            if (flags & FLAG_ACC) v += C[idx];
            if (flags & FLAG_RELU) v = fmaxf(v, 0.f);
            C[idx] = v;
        }
    }
}

// ---------------- fused pair GEMM: hdn2 = relu( relu(Ah[h]+Ao[n]) @ W_a2 + b_a2 ) ----
// M=16384 (p = h*256+n), K=2048, N=1024
__global__ void pairgemm(const float* __restrict__ Ah, const float* __restrict__ Ao,
                         const float* __restrict__ B, const float* __restrict__ bias,
                         float* __restrict__ C)
{
    __shared__ float As[16][64];
    __shared__ float Bs[16][64];
    const int row0 = blockIdx.y * 64;
    const int col0 = blockIdx.x * 64;
    const int t = threadIdx.x;
    const int ty = t >> 4, tx = t & 15;

    float acc[4][4] = {};

    for (int k0 = 0; k0 < 2048; k0 += 16) {
        #pragma unroll
        for (int i = 0; i < 4; i++) {
            int idx = t + i * 256;
            int r = idx >> 4, c = idx & 15;
            int grow = row0 + r;
            int h = grow >> 8, n = grow & 255;
            As[c][r] = fmaxf(Ah[h * 2048 + k0 + c] + Ao[n * 2048 + k0 + c], 0.f);
        }
        #pragma unroll
        for (int i = 0; i < 4; i++) {
            int idx = t + i * 256;
            int r = idx >> 6, c = idx & 63;
            Bs[r][c] = B[(size_t)(k0 + r) * 1024 + (col0 + c)];
        }
        __syncthreads();
        #pragma unroll
        for (int k = 0; k < 16; k++) {
            float a[4], b[4];
            #pragma unroll
            for (int i = 0; i < 4; i++) a[i] = As[k][ty * 4 + i];
            #pragma unroll
            for (int j = 0; j < 4; j++) b[j] = Bs[k][tx * 4 + j];
            #pragma unroll
            for (int i = 0; i < 4; i++)
                #pragma unroll
                for (int j = 0; j < 4; j++)
                    acc[i][j] += a[i] * b[j];
        }
        __syncthreads();
    }

    #pragma unroll
    for (int i = 0; i < 4; i++) {
        int row = row0 + ty * 4 + i;
        #pragma unroll
        for (int j = 0; j < 4; j++) {
            int col = col0 + tx * 4 + j;
            float v = fmaxf(acc[i][j] + bias[col], 0.f);
            C[(size_t)row * 1024 + col] = v;
        }
    }
}

// ---------------- adj = sigmoid(hdn2 @ W_a3 + b_a3), one warp per pair --------------
__global__ void adj_k(const float* __restrict__ hdn2, const float* __restrict__ w3,
                      const float* __restrict__ b3, float* __restrict__ adj)
{
    int p = blockIdx.x * 8 + (threadIdx.x >> 5);
    int lane = threadIdx.x & 31;
    const float* row = hdn2 + (size_t)p * 1024;
    float s = 0.f;
    #pragma unroll 4
    for (int j = lane; j < 1024; j += 32) s += row[j] * w3[j];
    #pragma unroll
    for (int o = 16; o > 0; o >>= 1) s += __shfl_xor_sync(0xffffffffu, s, o);
    if (lane == 0) adj[p] = 1.f / (1.f + expf(-(s + b3[0])));
}

// ---------------- agg_o[h,e] = hs_sa[h,e]*sum_n adj*om - sum_n adj*om*ns_sa ---------
__global__ void aggo_k(const float* __restrict__ adj, const float* __restrict__ obj,
                       const float* __restrict__ nssa, float* __restrict__ out)
{
    int h = blockIdx.y;
    int e = blockIdx.x * 128 + threadIdx.x;
    __shared__ float sa[256];
    for (int i = threadIdx.x; i < 256; i += 128) sa[i] = adj[h * 256 + i];
    __syncthreads();
    float a1 = 0.f, a2 = 0.f;
    #pragma unroll 4
    for (int n = 0; n < 256; n++) {
        float a = sa[n];
        float om = obj[n * 1024 + e];
        float ns = nssa[n * 1024 + e];
        a1 += a * om;
        a2 += a * om * ns;
    }
    out[h * 1024 + e] = nssa[h * 1024 + e] * a1 - a2;
}

// ---------------- agg_h[n,e] = ns_sa[n,e]*sum_h adj*hm - sum_h adj*hm*hs_sa ---------
__global__ void aggh_k(const float* __restrict__ adj, const float* __restrict__ hum,
                       const float* __restrict__ nssa, float* __restrict__ out)
{
    int n = blockIdx.y;
    int e = blockIdx.x * 128 + threadIdx.x;
    __shared__ float sa[64];
    if (threadIdx.x < 64) sa[threadIdx.x] = adj[threadIdx.x * 256 + n];
    __syncthreads();
    float a1 = 0.f, a2 = 0.f;
    #pragma unroll 4
    for (int h = 0; h < 64; h++) {
        float a = sa[h];
        float hm = hum[h * 1024 + e];
        float hs = nssa[h * 1024 + e];
        a1 += a * hm;
        a2 += a * hm * hs;
    }
    out[n * 1024 + e] = nssa[n * 1024 + e] * a1 - a2;
}

// ---------------- helpers ----------------
__global__ void copy_k(float* __restrict__ dst, const float* __restrict__ src, int n)
{
    int i = blockIdx.x * blockDim.x + threadIdx.x;
    if (i < n) dst[i] = src[i];
}

// detect class_mask dtype from its first 9360 bytes (always safe to read)
__global__ void detect_k(const unsigned char* __restrict__ cm)
{
    __shared__ int s_f, s_nz;
    if (threadIdx.x == 0) { s_f = 0; s_nz = 0; }
    __syncthreads();
    int lf = 0, lnz = 0;
    for (int i = threadIdx.x; i < 9360; i += blockDim.x) {
        unsigned char b = cm[i];
        int m4 = i & 3;
        if (m4 == 3 && b == 0x3F) lf = 1;
        if (m4 != 0 && b != 0) lnz = 1;
    }
    if (lf) atomicOr(&s_f, 1);
    if (lnz) atomicOr(&s_nz, 1);
    __syncthreads();
    if (threadIdx.x == 0) {
        g_mask_mode = s_f ? 2 : (s_nz ? 0 : 1);
    }
}

__device__ __forceinline__ float lisf(float x)
{
    return 8.3f / (1.f + expf(12.f - 10.f * x));
}

// ---------------- final gather: one block per kept pair row ----------------
__global__ void out_k(const float* __restrict__ hfin, const float* __restrict__ efin,
                      const float* __restrict__ nsp, const float* __restrict__ adj,
                      const float* __restrict__ scores, const int* __restrict__ labels,
                      const void* __restrict__ cmask, float* __restrict__ out)
{
    int p = blockIdx.x;                 // 0..16319
    int x = p / 255;
    int r = p % 255;
    int y = (r < x) ? r : r + 1;

    float scale = adj[x * 256 + y] * lisf(scores[x]) * lisf(scores[y]);
    int lab = labels[y];
    int mode = g_mask_mode;

    const float* hx = hfin + x * 1024;
    const float* sx = nsp + x * 1024;
    const float* ey = efin + y * 1024;
    const float* ny = nsp + y * 1024;
    float* o = out + (size_t)p * OUTC;

    for (int c = threadIdx.x; c < OUTC; c += blockDim.x) {
        float v;
        if (c < 1024)       v = hx[c];
        else if (c < 2048)  v = sx[c - 1024];
        else if (c < 3072)  v = ey[c - 2048];
        else if (c < 4096)  v = ny[c - 3072];
        else {
            int j = c - 4096;
            float m;
            if (mode == 0)      m = ((const unsigned char*)cmask)[lab * NCLS + j] ? 1.f : 0.f;
            else if (mode == 1) m = ((const int*)cmask)[lab * NCLS + j] ? 1.f : 0.f;
            else                m = ((const float*)cmask)[lab * NCLS + j];
            v = scale * m;
        }
        o[c] = v;
    }
}

// ---------------- host ----------------
static inline void launch_gemm(const float* A, const float* B, const float* bias,
                               float* C, int M, int N, int K, int flags)
{
    dim3 grid(N / 64, M / 64);
    gemm64<<<grid, 256>>>(A, B, bias, C, M, N, K, flags);
}

extern "C" void kernel_launch(void* const* d_in, const int* in_sizes, int n_in,
                              void* d_out, int out_size)
{
    // ---- bind inputs by element-count pattern (robust to ordering) ----
    const float *box = 0, *nsp = 0, *scores = 0;
    const int *labels = 0;
    const void *cmask = 0;
    const float *W_bh1 = 0, *b_bh1 = 0, *W_bh2 = 0, *b_bh2 = 0, *W_sa = 0;
    const float *W_a1 = 0, *b_a1 = 0, *W_a2 = 0, *b_a2 = 0, *W_a3 = 0, *b_a3 = 0;
    const float *W_hm = 0, *b_hm = 0, *W_om = 0, *b_om = 0, *W_hu = 0, *W_ou = 0;

    int c256 = 0, c1k = 0, c1m = 0, c2m = 0;
    for (int i = 0; i < n_in; i++) {
        const void* p = d_in[i];
        switch (in_sizes[i]) {
            case 3211264:  box = (const float*)p; break;
            case 262144:   nsp = (const float*)p; break;
            case 256:      if (c256++ == 0) scores = (const float*)p; else labels = (const int*)p; break;
            case 9360:     cmask = p; break;
            case 12845056: W_bh1 = (const float*)p; break;
            case 1024:
                switch (c1k++) {
                    case 0: b_bh1 = (const float*)p; break;
                    case 1: b_bh2 = (const float*)p; break;
                    case 2: b_a2  = (const float*)p; break;
                    case 3: W_a3  = (const float*)p; break;
                    case 4: b_hm  = (const float*)p; break;
                    case 5: b_om  = (const float*)p; break;
                } break;
            case 1048576:
                switch (c1m++) {
                    case 0: W_bh2 = (const float*)p; break;
                    case 1: W_sa  = (const float*)p; break;
                    case 2: W_hm  = (const float*)p; break;
                    case 3: W_om  = (const float*)p; break;
                } break;
            case 8388608:  W_a1 = (const float*)p; break;
            case 2048:     b_a1 = (const float*)p; break;
            case 2097152:
                switch (c2m++) {
                    case 0: W_a2 = (const float*)p; break;
                    case 1: W_hu = (const float*)p; break;
                    case 2: W_ou = (const float*)p; break;
                } break;
            case 1:        b_a3 = (const float*)p; break;
            default: break;
        }
    }

    // ---- scratch pointers ----
    float *enc1, *encA, *encB, *hA, *hB, *nssa, *Ah, *Ao, *hdn2, *adj, *obj, *hum, *aggo, *aggh;
    cudaGetSymbolAddress((void**)&enc1, g_enc1);
    cudaGetSymbolAddress((void**)&encA, g_encA);
    cudaGetSymbolAddress((void**)&encB, g_encB);
    cudaGetSymbolAddress((void**)&hA,   g_hA);
    cudaGetSymbolAddress((void**)&hB,   g_hB);
    cudaGetSymbolAddress((void**)&nssa, g_nssa);
    cudaGetSymbolAddress((void**)&Ah,   g_Ah);
    cudaGetSymbolAddress((void**)&Ao,   g_Ao);
    cudaGetSymbolAddress((void**)&hdn2, g_hdn2);
    cudaGetSymbolAddress((void**)&adj,  g_adj);
    cudaGetSymbolAddress((void**)&obj,  g_obj);
    cudaGetSymbolAddress((void**)&hum,  g_hum);
    cudaGetSymbolAddress((void**)&aggo, g_aggo);
    cudaGetSymbolAddress((void**)&aggh, g_aggh);

    // ---- encoder ----
    launch_gemm(box,  W_bh1, b_bh1, enc1, NOBJ, EDIM, 12544, FLAG_RELU);
    launch_gemm(enc1, W_bh2, b_bh2, encA, NOBJ, EDIM, 1024,  FLAG_RELU);
    launch_gemm(nsp,  W_sa,  0,     nssa, NOBJ, EDIM, 1024,  0);
    copy_k<<<(NHUM * EDIM + 255) / 256, 256>>>(hA, encA, NHUM * EDIM);

    float* enc_in = encA;  float* enc_out = encB;
    float* h_in = hA;      float* h_out = hB;

    for (int it = 0; it < 2; it++) {
        // A_h = [h_enc | h_sp] @ W_a1[:2048] + b_a1   (h_sp = nsp rows 0..63)
        launch_gemm(h_in, W_a1,                0,    Ah, NHUM, 2048, 1024, 0);
        launch_gemm(nsp,  W_a1 + 1024 * 2048,  b_a1, Ah, NHUM, 2048, 1024, FLAG_ACC);
        // A_o = [enc | node_spatial] @ W_a1[2048:]
        launch_gemm(enc_in, W_a1 + 2048 * 2048, 0, Ao, NOBJ, 2048, 1024, 0);
        launch_gemm(nsp,    W_a1 + 3072 * 2048, 0, Ao, NOBJ, 2048, 1024, FLAG_ACC);

        // hdn2 = relu( relu(Ah[h]+Ao[n]) @ W_a2 + b_a2 )
        pairgemm<<<dim3(16, 256), 256>>>(Ah, Ao, W_a2, b_a2, hdn2);

        // adj = sigmoid(hdn2 @ W_a3 + b_a3)
        adj_k<<<NPAIR / 8, 256>>>(hdn2, W_a3, b_a3, adj);

        // obj_msg, agg_o
        launch_gemm(enc_in, W_om, b_om, obj, NOBJ, EDIM, 1024, FLAG_RELU);
        aggo_k<<<dim3(8, NHUM), 128>>>(adj, obj, nssa, aggo);

        // h_enc = [h_enc | agg_o] @ W_hu
        launch_gemm(h_in, W_hu,               0, h_out, NHUM, EDIM, 1024, 0);
        launch_gemm(aggo, W_hu + 1024 * 1024, 0, h_out, NHUM, EDIM, 1024, FLAG_ACC);

        // hum_msg, agg_h
        launch_gemm(h_out, W_hm, b_hm, hum, NHUM, EDIM, 1024, FLAG_RELU);
        aggh_k<<<dim3(8, NOBJ), 128>>>(adj, hum, nssa, aggh);

        // enc = [enc | agg_h] @ W_ou
        launch_gemm(enc_in, W_ou,               0, enc_out, NOBJ, EDIM, 1024, 0);
        launch_gemm(aggh,   W_ou + 1024 * 1024, 0, enc_out, NOBJ, EDIM, 1024, FLAG_ACC);

        // ping-pong
        float* t;
        t = enc_in; enc_in = enc_out; enc_out = t;
        t = h_in;   h_in = h_out;     h_out = t;
    }

    // ---- final gather ----
    detect_k<<<1, 256>>>((const unsigned char*)cmask);
    out_k<<<NKEEP, 128>>>(h_in, enc_in, nsp, adj, scores, labels, cmask, (float*)d_out);
}

// round 4
// speedup vs baseline: 1.9875x; 1.9800x over previous
#include <cuda_runtime.h>
#include <cuda_bf16.h>
#include <math.h>
#include <stdint.h>

// ---------------- problem constants ----------------
#define NOBJ 256
#define NHUM 64
#define EDIM 1024
#define NPAIR 16384      // 64*256
#define NKEEP 16320
#define OUTC 4213        // 4*1024 + 117
#define NCLS 117

// ---------------- scratch (static device memory; no allocs) ----------------
__device__ float g_enc1[NOBJ*EDIM];
__device__ float g_encA[NOBJ*EDIM];
__device__ float g_encB[NOBJ*EDIM];
__device__ float g_hA[NHUM*EDIM];
__device__ float g_hB[NHUM*EDIM];
__device__ float g_nssa[NOBJ*EDIM];
__device__ float g_Ah[NHUM*2048];
__device__ float g_Ao[NOBJ*2048];
__device__ float g_adjp[NPAIR];
__device__ float g_adj[NPAIR];
__device__ float g_obj[NOBJ*EDIM];
__device__ float g_hum[NHUM*EDIM];
__device__ float g_aggo[NHUM*EDIM];
__device__ float g_aggh[NOBJ*EDIM];
__device__ __nv_bfloat16 g_wthi[2048*1024];   // W_a2^T split, [n(1024)][k(2048)]
__device__ __nv_bfloat16 g_wtlo[2048*1024];
__device__ int   g_mask_mode;   // 0=uint8(bool), 1=int32, 2=float32

__device__ __forceinline__ uint32_t smem_u32(const void* p) {
    uint32_t a;
    asm("{ .reg .u64 t; cvta.to.shared.u64 t, %1; cvt.u32.u64 %0, t; }" : "=r"(a) : "l"(p));
    return a;
}

// ---------------- generic fp32 tiled GEMM: C = act(A@B [+bias] [+C]) ----------------
#define FLAG_ACC  1
#define FLAG_RELU 2

__global__ void gemm64(const float* __restrict__ A, const float* __restrict__ B,
                       const float* __restrict__ bias, float* __restrict__ C,
                       int M, int N, int K, int flags)
{
    __shared__ float As[16][64];
    __shared__ float Bs[16][64];
    const int row0 = blockIdx.y * 64;
    const int col0 = blockIdx.x * 64;
    const int t = threadIdx.x;
    const int ty = t >> 4, tx = t & 15;

    float acc[4][4] = {};

    for (int k0 = 0; k0 < K; k0 += 16) {
        #pragma unroll
        for (int i = 0; i < 4; i++) {
            int idx = t + i * 256;
            int r = idx >> 4, c = idx & 15;
            As[c][r] = A[(size_t)(row0 + r) * K + (k0 + c)];
        }
        #pragma unroll
        for (int i = 0; i < 4; i++) {
            int idx = t + i * 256;
            int r = idx >> 6, c = idx & 63;
            Bs[r][c] = B[(size_t)(k0 + r) * N + (col0 + c)];
        }
        __syncthreads();
        #pragma unroll
        for (int k = 0; k < 16; k++) {
            float a[4], b[4];
            #pragma unroll
            for (int i = 0; i < 4; i++) a[i] = As[k][ty * 4 + i];
            #pragma unroll
            for (int j = 0; j < 4; j++) b[j] = Bs[k][tx * 4 + j];
            #pragma unroll
            for (int i = 0; i < 4; i++)
                #pragma unroll
                for (int j = 0; j < 4; j++)
                    acc[i][j] += a[i] * b[j];
        }
        __syncthreads();
    }

    #pragma unroll
    for (int i = 0; i < 4; i++) {
        int row = row0 + ty * 4 + i;
        #pragma unroll
        for (int j = 0; j < 4; j++) {
            int col = col0 + tx * 4 + j;
            size_t idx = (size_t)row * N + col;
            float v = acc[i][j];
            if (bias) v += bias[col];
            if (flags & FLAG_ACC) v += C[idx];
            if (flags & FLAG_RELU) v = fmaxf(v, 0.f);
            C[idx] = v;
        }
    }
}

// ---------- W_a2 transpose + bf16 hi/lo split: Wt[n][k] = W[k][n] ----------
__global__ void convw_k(const float* __restrict__ W,
                        __nv_bfloat16* __restrict__ hi, __nv_bfloat16* __restrict__ lo)
{
    __shared__ float t[32][33];
    int kb = blockIdx.x * 32, nb = blockIdx.y * 32;
    int tx = threadIdx.x, ty = threadIdx.y;   // 32x8
    #pragma unroll
    for (int i = 0; i < 4; i++)
        t[ty + 8 * i][tx] = W[(size_t)(kb + ty + 8 * i) * 1024 + nb + tx];
    __syncthreads();
    #pragma unroll
    for (int i = 0; i < 4; i++) {
        float v = t[tx][ty + 8 * i];
        __nv_bfloat16 h = __float2bfloat16(v);
        size_t oi = (size_t)(nb + ty + 8 * i) * 2048 + kb + tx;
        hi[oi] = h;
        lo[oi] = __float2bfloat16(v - __bfloat162float(h));
    }
}

__global__ void zero_k(float* __restrict__ p, int n)
{
    int i = blockIdx.x * blockDim.x + threadIdx.x;
    if (i < n) p[i] = 0.f;
}

// ================= mma.sync helpers =================
__device__ __forceinline__ void mma16816(float* c, const uint32_t* a, const uint32_t* b)
{
    asm volatile("mma.sync.aligned.m16n8k16.row.col.f32.bf16.bf16.f32 "
                 "{%0,%1,%2,%3}, {%4,%5,%6,%7}, {%8,%9}, {%0,%1,%2,%3};"
                 : "+f"(c[0]), "+f"(c[1]), "+f"(c[2]), "+f"(c[3])
                 : "r"(a[0]), "r"(a[1]), "r"(a[2]), "r"(a[3]), "r"(b[0]), "r"(b[1]));
}
__device__ __forceinline__ void ldmx4(uint32_t* d, uint32_t addr)
{
    asm volatile("ldmatrix.sync.aligned.m8n8.x4.shared.b16 {%0,%1,%2,%3}, [%4];"
                 : "=r"(d[0]), "=r"(d[1]), "=r"(d[2]), "=r"(d[3]) : "r"(addr));
}
__device__ __forceinline__ void ldmx2(uint32_t* d, uint32_t addr)
{
    asm volatile("ldmatrix.sync.aligned.m8n8.x2.shared.b16 {%0,%1}, [%2];"
                 : "=r"(d[0]), "=r"(d[1]) : "r"(addr));
}

// smem layout for pair_mma (bytes); tiles are 128 rows x 72 bf16 (144B stride)
#define OA_HI 0
#define OA_LO 18432
#define OW_HI 36864
#define OW_LO 55296
#define OSRED 73728
#define OSB2  74240
#define OSW3  74752
#define PM_SMEM 75264

// ---------- fused pair MMA: D = relu(Ah[h]+Ao[n]) @ W_a2 (bf16 hi/lo, 3 MMAs) ----
// epilogue: adjp[row] += sum_col relu(D+b_a2)*w3   (128x128 tile per CTA)
__global__ void __launch_bounds__(256)
pair_mma_k(const float* __restrict__ Ah, const float* __restrict__ Ao,
           const __nv_bfloat16* __restrict__ Wthi, const __nv_bfloat16* __restrict__ Wtlo,
           const float* __restrict__ b2, const float* __restrict__ w3,
           float* __restrict__ adjp)
{
    extern __shared__ char smem[];
    uint32_t sb = smem_u32(smem);
    const int tid = threadIdx.x;
    const int wid = tid >> 5, lid = tid & 31;
    const int col0 = blockIdx.x * 128;
    const int row0 = blockIdx.y * 128;
    const int h = row0 >> 8;          // tile never crosses an h boundary
    const int nb = row0 & 255;
    const int warp_row = wid >> 2;    // 0..1
    const int warp_col = wid & 3;     // 0..3

    if (tid < 128) {
        *(float*)(smem + OSB2 + tid * 4) = b2[col0 + tid];
        *(float*)(smem + OSW3 + tid * 4) = w3[col0 + tid];
        *(float*)(smem + OSRED + tid * 4) = 0.f;
    }

    float acc[4][4][4];
    #pragma unroll
    for (int i = 0; i < 4; i++)
        #pragma unroll
        for (int j = 0; j < 4; j++)
            #pragma unroll
            for (int q = 0; q < 4; q++) acc[i][j][q] = 0.f;

    const float* ahrow = Ah + (size_t)h * 2048;

    for (int c = 0; c < 32; c++) {
        const int k0 = c * 64;
        __syncthreads();
        // ---- fill smem: A tiles (relu(Ah+Ao) -> hi/lo), W tiles (pre-split) ----
        #pragma unroll
        for (int gi = 0; gi < 4; gi++) {
            int g = tid + gi * 256;          // 0..1023
            int r = g >> 3;
            int kk = (g & 7) * 8;
            const float4* pa = (const float4*)(ahrow + k0 + kk);
            const float4* po = (const float4*)(Ao + (size_t)(nb + r) * 2048 + k0 + kk);
            float4 a0 = pa[0], a1 = pa[1];
            float4 o0 = po[0], o1 = po[1];
            float v[8];
            v[0] = fmaxf(a0.x + o0.x, 0.f); v[1] = fmaxf(a0.y + o0.y, 0.f);
            v[2] = fmaxf(a0.z + o0.z, 0.f); v[3] = fmaxf(a0.w + o0.w, 0.f);
            v[4] = fmaxf(a1.x + o1.x, 0.f); v[5] = fmaxf(a1.y + o1.y, 0.f);
            v[6] = fmaxf(a1.z + o1.z, 0.f); v[7] = fmaxf(a1.w + o1.w, 0.f);
            uint32_t hp[4], lp[4];
            #pragma unroll
            for (int q = 0; q < 4; q++) {
                __nv_bfloat16 h0 = __float2bfloat16(v[2*q]);
                __nv_bfloat16 h1 = __float2bfloat16(v[2*q+1]);
                __nv_bfloat16 l0 = __float2bfloat16(v[2*q]   - __bfloat162float(h0));
                __nv_bfloat16 l1 = __float2bfloat16(v[2*q+1] - __bfloat162float(h1));
                __nv_bfloat162 hh = __nv_bfloat162(h0, h1);
                __nv_bfloat162 ll = __nv_bfloat162(l0, l1);
                hp[q] = *(uint32_t*)&hh;
                lp[q] = *(uint32_t*)&ll;
            }
            uint32_t off = (uint32_t)(r * 144 + kk * 2);
            *(uint4*)(smem + OA_HI + off) = make_uint4(hp[0], hp[1], hp[2], hp[3]);
            *(uint4*)(smem + OA_LO + off) = make_uint4(lp[0], lp[1], lp[2], lp[3]);
            size_t wi = (size_t)(col0 + r) * 2048 + k0 + kk;
            *(uint4*)(smem + OW_HI + off) = *(const uint4*)(Wthi + wi);
            *(uint4*)(smem + OW_LO + off) = *(const uint4*)(Wtlo + wi);
        }
        __syncthreads();

        // ---- compute chunk ----
        #pragma unroll
        for (int ks = 0; ks < 4; ks++) {
            const int kk = ks * 16;
            uint32_t bh[4][2], bl[4][2];
            const int l2 = lid & 15;
            const uint32_t bro = (uint32_t)((l2 & 7) * 144 + (kk + ((l2 & 8) ? 8 : 0)) * 2);
            #pragma unroll
            for (int an = 0; an < 4; an++) {
                uint32_t nbase = (uint32_t)((warp_col * 32 + an * 8) * 144);
                ldmx2(bh[an], sb + OW_HI + nbase + bro);
                ldmx2(bl[an], sb + OW_LO + nbase + bro);
            }
            const uint32_t aro = (uint32_t)(((lid & 7) + ((lid & 8) ? 8 : 0)) * 144
                                          + (kk + ((lid & 16) ? 8 : 0)) * 2);
            #pragma unroll
            for (int am = 0; am < 4; am++) {
                uint32_t mbase = (uint32_t)((warp_row * 64 + am * 16) * 144);
                uint32_t ah4[4], al4[4];
                ldmx4(ah4, sb + OA_HI + mbase + aro);
                ldmx4(al4, sb + OA_LO + mbase + aro);
                #pragma unroll
                for (int an = 0; an < 4; an++) {
                    mma16816(acc[am][an], ah4, bh[an]);
                    mma16816(acc[am][an], ah4, bl[an]);
                    mma16816(acc[am][an], al4, bh[an]);
                }
            }
        }
    }

    // ---- fused epilogue: row-partials of relu(D + b2) . w3 ----
    const float* b2s = (const float*)(smem + OSB2);
    const float* w3s = (const float*)(smem + OSW3);
    float* sred = (float*)(smem + OSRED);
    #pragma unroll
    for (int am = 0; am < 4; am++) {
        float pl = 0.f, ph = 0.f;
        #pragma unroll
        for (int an = 0; an < 4; an++) {
            int cb = warp_col * 32 + an * 8 + 2 * (lid & 3);
            float w0 = w3s[cb], w1 = w3s[cb + 1];
            float bb0 = b2s[cb], bb1 = b2s[cb + 1];
            pl += fmaxf(acc[am][an][0] + bb0, 0.f) * w0 + fmaxf(acc[am][an][1] + bb1, 0.f) * w1;
            ph += fmaxf(acc[am][an][2] + bb0, 0.f) * w0 + fmaxf(acc[am][an][3] + bb1, 0.f) * w1;
        }
        pl += __shfl_xor_sync(0xffffffffu, pl, 1);
        pl += __shfl_xor_sync(0xffffffffu, pl, 2);
        ph += __shfl_xor_sync(0xffffffffu, ph, 1);
        ph += __shfl_xor_sync(0xffffffffu, ph, 2);
        if ((lid & 3) == 0) {
            int rloc = warp_row * 64 + am * 16 + (lid >> 2);
            atomicAdd(sred + rloc, pl);
            atomicAdd(sred + rloc + 8, ph);
        }
    }
    __syncthreads();
    if (tid < 128) atomicAdd(adjp + row0 + tid, sred[tid]);
}

// ---------------- adj = sigmoid(adjp + b_a3) ----------------
__global__ void adjfin_k(const float* __restrict__ adjp, const float* __restrict__ b3,
                         float* __restrict__ adj)
{
    int p = blockIdx.x * 256 + threadIdx.x;
    if (p < NPAIR) adj[p] = 1.f / (1.f + expf(-(adjp[p] + b3[0])));
}

// ---------------- agg_o[h,e] ----------------
__global__ void aggo_k(const float* __restrict__ adj, const float* __restrict__ obj,
                       const float* __restrict__ nssa, float* __restrict__ out)
{
    int h = blockIdx.y;
    int e = blockIdx.x * 128 + threadIdx.x;
    __shared__ float sa[256];
    for (int i = threadIdx.x; i < 256; i += 128) sa[i] = adj[h * 256 + i];
    __syncthreads();
    float a1 = 0.f, a2 = 0.f;
    #pragma unroll 4
    for (int n = 0; n < 256; n++) {
        float a = sa[n];
        float om = obj[n * 1024 + e];
        float ns = nssa[n * 1024 + e];
        a1 += a * om;
        a2 += a * om * ns;
    }
    out[h * 1024 + e] = nssa[h * 1024 + e] * a1 - a2;
}

// ---------------- agg_h[n,e] ----------------
__global__ void aggh_k(const float* __restrict__ adj, const float* __restrict__ hum,
                       const float* __restrict__ nssa, float* __restrict__ out)
{
    int n = blockIdx.y;
    int e = blockIdx.x * 128 + threadIdx.x;
    __shared__ float sa[64];
    if (threadIdx.x < 64) sa[threadIdx.x] = adj[threadIdx.x * 256 + n];
    __syncthreads();
    float a1 = 0.f, a2 = 0.f;
    #pragma unroll 4
    for (int h = 0; h < 64; h++) {
        float a = sa[h];
        float hm = hum[h * 1024 + e];
        float hs = nssa[h * 1024 + e];
        a1 += a * hm;
        a2 += a * hm * hs;
    }
    out[n * 1024 + e] = nssa[n * 1024 + e] * a1 - a2;
}

// ---------------- helpers ----------------
__global__ void copy_k(float* __restrict__ dst, const float* __restrict__ src, int n)
{
    int i = blockIdx.x * blockDim.x + threadIdx.x;
    if (i < n) dst[i] = src[i];
}

__global__ void detect_k(const unsigned char* __restrict__ cm)
{
    __shared__ int s_f, s_nz;
    if (threadIdx.x == 0) { s_f = 0; s_nz = 0; }
    __syncthreads();
    int lf = 0, lnz = 0;
    for (int i = threadIdx.x; i < 9360; i += blockDim.x) {
        unsigned char b = cm[i];
        int m4 = i & 3;
        if (m4 == 3 && b == 0x3F) lf = 1;
        if (m4 != 0 && b != 0) lnz = 1;
    }
    if (lf) atomicOr(&s_f, 1);
    if (lnz) atomicOr(&s_nz, 1);
    __syncthreads();
    if (threadIdx.x == 0) g_mask_mode = s_f ? 2 : (s_nz ? 0 : 1);
}

__device__ __forceinline__ float lisf(float x)
{
    return 8.3f / (1.f + expf(12.f - 10.f * x));
}

// ---------------- final gather ----------------
__global__ void out_k(const float* __restrict__ hfin, const float* __restrict__ efin,
                      const float* __restrict__ nsp, const float* __restrict__ adj,
                      const float* __restrict__ scores, const int* __restrict__ labels,
                      const void* __restrict__ cmask, float* __restrict__ out)
{
    int p = blockIdx.x;
    int x = p / 255;
    int r = p % 255;
    int y = (r < x) ? r : r + 1;

    float scale = adj[x * 256 + y] * lisf(scores[x]) * lisf(scores[y]);
    int lab = labels[y];
    int mode = g_mask_mode;

    const float* hx = hfin + x * 1024;
    const float* sx = nsp + x * 1024;
    const float* ey = efin + y * 1024;
    const float* ny = nsp + y * 1024;
    float* o = out + (size_t)p * OUTC;

    for (int c = threadIdx.x; c < OUTC; c += blockDim.x) {
        float v;
        if (c < 1024)       v = hx[c];
        else if (c < 2048)  v = sx[c - 1024];
        else if (c < 3072)  v = ey[c - 2048];
        else if (c < 4096)  v = ny[c - 3072];
        else {
            int j = c - 4096;
            float m;
            if (mode == 0)      m = ((const unsigned char*)cmask)[lab * NCLS + j] ? 1.f : 0.f;
            else if (mode == 1) m = ((const int*)cmask)[lab * NCLS + j] ? 1.f : 0.f;
            else                m = ((const float*)cmask)[lab * NCLS + j];
            v = scale * m;
        }
        o[c] = v;
    }
}

// ---------------- host ----------------
static inline void launch_gemm(const float* A, const float* B, const float* bias,
                               float* C, int M, int N, int K, int flags)
{
    dim3 grid(N / 64, M / 64);
    gemm64<<<grid, 256>>>(A, B, bias, C, M, N, K, flags);
}

extern "C" void kernel_launch(void* const* d_in, const int* in_sizes, int n_in,
                              void* d_out, int out_size)
{
    const float *box = 0, *nsp = 0, *scores = 0;
    const int *labels = 0;
    const void *cmask = 0;
    const float *W_bh1 = 0, *b_bh1 = 0, *W_bh2 = 0, *b_bh2 = 0, *W_sa = 0;
    const float *W_a1 = 0, *b_a1 = 0, *W_a2 = 0, *b_a2 = 0, *W_a3 = 0, *b_a3 = 0;
    const float *W_hm = 0, *b_hm = 0, *W_om = 0, *b_om = 0, *W_hu = 0, *W_ou = 0;

    int c256 = 0, c1k = 0, c1m = 0, c2m = 0;
    for (int i = 0; i < n_in; i++) {
        const void* p = d_in[i];
        switch (in_sizes[i]) {
            case 3211264:  box = (const float*)p; break;
            case 262144:   nsp = (const float*)p; break;
            case 256:      if (c256++ == 0) scores = (const float*)p; else labels = (const int*)p; break;
            case 9360:     cmask = p; break;
            case 12845056: W_bh1 = (const float*)p; break;
            case 1024:
                switch (c1k++) {
                    case 0: b_bh1 = (const float*)p; break;
                    case 1: b_bh2 = (const float*)p; break;
                    case 2: b_a2  = (const float*)p; break;
                    case 3: W_a3  = (const float*)p; break;
                    case 4: b_hm  = (const float*)p; break;
                    case 5: b_om  = (const float*)p; break;
                } break;
            case 1048576:
                switch (c1m++) {
                    case 0: W_bh2 = (const float*)p; break;
                    case 1: W_sa  = (const float*)p; break;
                    case 2: W_hm  = (const float*)p; break;
                    case 3: W_om  = (const float*)p; break;
                } break;
            case 8388608:  W_a1 = (const float*)p; break;
            case 2048:     b_a1 = (const float*)p; break;
            case 2097152:
                switch (c2m++) {
                    case 0: W_a2 = (const float*)p; break;
                    case 1: W_hu = (const float*)p; break;
                    case 2: W_ou = (const float*)p; break;
                } break;
            case 1:        b_a3 = (const float*)p; break;
            default: break;
        }
    }

    float *enc1, *encA, *encB, *hA, *hB, *nssa, *Ah, *Ao, *adjp, *adj, *obj, *hum, *aggo, *aggh;
    __nv_bfloat16 *wthi, *wtlo;
    cudaGetSymbolAddress((void**)&enc1, g_enc1);
    cudaGetSymbolAddress((void**)&encA, g_encA);
    cudaGetSymbolAddress((void**)&encB, g_encB);
    cudaGetSymbolAddress((void**)&hA,   g_hA);
    cudaGetSymbolAddress((void**)&hB,   g_hB);
    cudaGetSymbolAddress((void**)&nssa, g_nssa);
    cudaGetSymbolAddress((void**)&Ah,   g_Ah);
    cudaGetSymbolAddress((void**)&Ao,   g_Ao);
    cudaGetSymbolAddress((void**)&adjp, g_adjp);
    cudaGetSymbolAddress((void**)&adj,  g_adj);
    cudaGetSymbolAddress((void**)&obj,  g_obj);
    cudaGetSymbolAddress((void**)&hum,  g_hum);
    cudaGetSymbolAddress((void**)&aggo, g_aggo);
    cudaGetSymbolAddress((void**)&aggh, g_aggh);
    cudaGetSymbolAddress((void**)&wthi, g_wthi);
    cudaGetSymbolAddress((void**)&wtlo, g_wtlo);

    cudaFuncSetAttribute(pair_mma_k, cudaFuncAttributeMaxDynamicSharedMemorySize, PM_SMEM);

    // ---- encoder + invariants ----
    launch_gemm(box,  W_bh1, b_bh1, enc1, NOBJ, EDIM, 12544, FLAG_RELU);
    launch_gemm(enc1, W_bh2, b_bh2, encA, NOBJ, EDIM, 1024,  FLAG_RELU);
    launch_gemm(nsp,  W_sa,  0,     nssa, NOBJ, EDIM, 1024,  0);
    copy_k<<<(NHUM * EDIM + 255) / 256, 256>>>(hA, encA, NHUM * EDIM);
    convw_k<<<dim3(64, 32), dim3(32, 8)>>>(W_a2, wthi, wtlo);

    float* enc_in = encA;  float* enc_out = encB;
    float* h_in = hA;      float* h_out = hB;

    for (int it = 0; it < 2; it++) {
        // A_h = [h_enc | h_sp] @ W_a1[:2048] + b_a1
        launch_gemm(h_in, W_a1,                0,    Ah, NHUM, 2048, 1024, 0);
        launch_gemm(nsp,  W_a1 + 1024 * 2048,  b_a1, Ah, NHUM, 2048, 1024, FLAG_ACC);
        // A_o = [enc | node_spatial] @ W_a1[2048:]
        launch_gemm(enc_in, W_a1 + 2048 * 2048, 0, Ao, NOBJ, 2048, 1024, 0);
        launch_gemm(nsp,    W_a1 + 3072 * 2048, 0, Ao, NOBJ, 2048, 1024, FLAG_ACC);

        // adj pre-activation via fused mma pair GEMM (hdn2 never materialized)
        zero_k<<<NPAIR / 256, 256>>>(adjp, NPAIR);
        pair_mma_k<<<dim3(8, 128), 256, PM_SMEM>>>(Ah, Ao, wthi, wtlo, b_a2, W_a3, adjp);
        adjfin_k<<<NPAIR / 256, 256>>>(adjp, b_a3, adj);

        // obj_msg, agg_o
        launch_gemm(enc_in, W_om, b_om, obj, NOBJ, EDIM, 1024, FLAG_RELU);
        aggo_k<<<dim3(8, NHUM), 128>>>(adj, obj, nssa, aggo);

        // h_enc = [h_enc | agg_o] @ W_hu
        launch_gemm(h_in, W_hu,               0, h_out, NHUM, EDIM, 1024, 0);
        launch_gemm(aggo, W_hu + 1024 * 1024, 0, h_out, NHUM, EDIM, 1024, FLAG_ACC);

        // hum_msg, agg_h
        launch_gemm(h_out, W_hm, b_hm, hum, NHUM, EDIM, 1024, FLAG_RELU);
        aggh_k<<<dim3(8, NOBJ), 128>>>(adj, hum, nssa, aggh);

        // enc = [enc | agg_h] @ W_ou
        launch_gemm(enc_in, W_ou,               0, enc_out, NOBJ, EDIM, 1024, 0);
        launch_gemm(aggh,   W_ou + 1024 * 1024, 0, enc_out, NOBJ, EDIM, 1024, FLAG_ACC);

        float* t;
        t = enc_in; enc_in = enc_out; enc_out = t;
        t = h_in;   h_in = h_out;     h_out = t;
    }

    // ---- final gather ----
    detect_k<<<1, 256>>>((const unsigned char*)cmask);
    out_k<<<NKEEP, 128>>>(h_in, enc_in, nsp, adj, scores, labels, cmask, (float*)d_out);
}

// round 5
// speedup vs baseline: 2.2648x; 1.1395x over previous
#include <cuda_runtime.h>
#include <cuda_bf16.h>
#include <math.h>
#include <stdint.h>

// ---------------- problem constants ----------------
#define NOBJ 256
#define NHUM 64
#define EDIM 1024
#define NPAIR 16384
#define NKEEP 16320
#define OUTC 4213
#define NCLS 117

// flags
#define FLAG_ACC    1
#define FLAG_RELU   2
#define FLAG_ATOMIC 4

// ---------------- scratch (static device memory; no allocs) ----------------
__device__ float g_enc1[NOBJ*EDIM];
__device__ float g_encA[NOBJ*EDIM];
__device__ float g_encB[NOBJ*EDIM];
__device__ float g_hA[NHUM*EDIM];
__device__ float g_hB[NHUM*EDIM];
__device__ float g_nssa[NOBJ*EDIM];
__device__ float g_Ah[NHUM*2048];
__device__ float g_Ao[NOBJ*2048];
__device__ float g_adjp[NPAIR];
__device__ float g_adj[NPAIR];
__device__ float g_obj[NOBJ*EDIM];
__device__ float g_hum[NHUM*EDIM];
__device__ float g_aggo[NHUM*EDIM];
__device__ float g_aggh[NOBJ*EDIM];
__device__ int   g_mask_mode;

// pre-split transposed weights: [n][k] bf16 hi/lo
__device__ __nv_bfloat16 g_bh1hi[1024*12544];
__device__ __nv_bfloat16 g_bh1lo[1024*12544];
__device__ __nv_bfloat16 g_bh2hi[1024*1024];
__device__ __nv_bfloat16 g_bh2lo[1024*1024];
__device__ __nv_bfloat16 g_sahi[1024*1024];
__device__ __nv_bfloat16 g_salo[1024*1024];
__device__ __nv_bfloat16 g_omhi[1024*1024];
__device__ __nv_bfloat16 g_omlo[1024*1024];
__device__ __nv_bfloat16 g_hmhi[1024*1024];
__device__ __nv_bfloat16 g_hmlo[1024*1024];
__device__ __nv_bfloat16 g_a2hi[1024*2048];
__device__ __nv_bfloat16 g_a2lo[1024*2048];
__device__ __nv_bfloat16 g_a1hi[4*2048*1024];
__device__ __nv_bfloat16 g_a1lo[4*2048*1024];
__device__ __nv_bfloat16 g_huhi[2*1024*1024];
__device__ __nv_bfloat16 g_hulo[2*1024*1024];
__device__ __nv_bfloat16 g_ouhi[2*1024*1024];
__device__ __nv_bfloat16 g_oulo[2*1024*1024];

__device__ __forceinline__ uint32_t smem_u32(const void* p) {
    uint32_t a;
    asm("{ .reg .u64 t; cvta.to.shared.u64 t, %1; cvt.u32.u64 %0, t; }" : "=r"(a) : "l"(p));
    return a;
}
__device__ __forceinline__ void cpasync16(uint32_t saddr, const void* g) {
    asm volatile("{ .reg .u64 gg; cvta.to.global.u64 gg, %1; "
                 "cp.async.cg.shared.global [%0], [gg], 16; }"
                 :: "r"(saddr), "l"(g));
}
#define CP_COMMIT() asm volatile("cp.async.commit_group;")
#define CP_WAIT0()  asm volatile("cp.async.wait_group 0;")

// ================= mma.sync helpers =================
__device__ __forceinline__ void mma16816(float* c, const uint32_t* a, const uint32_t* b)
{
    asm volatile("mma.sync.aligned.m16n8k16.row.col.f32.bf16.bf16.f32 "
                 "{%0,%1,%2,%3}, {%4,%5,%6,%7}, {%8,%9}, {%0,%1,%2,%3};"
                 : "+f"(c[0]), "+f"(c[1]), "+f"(c[2]), "+f"(c[3])
                 : "r"(a[0]), "r"(a[1]), "r"(a[2]), "r"(a[3]), "r"(b[0]), "r"(b[1]));
}
__device__ __forceinline__ void ldmx4(uint32_t* d, uint32_t addr)
{
    asm volatile("ldmatrix.sync.aligned.m8n8.x4.shared.b16 {%0,%1,%2,%3}, [%4];"
                 : "=r"(d[0]), "=r"(d[1]), "=r"(d[2]), "=r"(d[3]) : "r"(addr));
}
__device__ __forceinline__ void ldmx2(uint32_t* d, uint32_t addr)
{
    asm volatile("ldmatrix.sync.aligned.m8n8.x2.shared.b16 {%0,%1}, [%2];"
                 : "=r"(d[0]), "=r"(d[1]) : "r"(addr));
}

// shared MMA chunk: 128x128 tile, K=64, tiles at stride 144B
__device__ __forceinline__ void mma_chunk(uint32_t abase_hi, uint32_t abase_lo,
                                          uint32_t wbase_hi, uint32_t wbase_lo,
                                          float acc[4][4][4], int lid,
                                          int warp_row, int warp_col)
{
    #pragma unroll
    for (int ks = 0; ks < 4; ks++) {
        const int kk = ks * 16;
        uint32_t bh[4][2], bl[4][2];
        const int l2 = lid & 15;
        const uint32_t bro = (uint32_t)((l2 & 7) * 144 + (kk + ((l2 & 8) ? 8 : 0)) * 2);
        #pragma unroll
        for (int an = 0; an < 4; an++) {
            uint32_t nbase = (uint32_t)((warp_col * 32 + an * 8) * 144);
            ldmx2(bh[an], wbase_hi + nbase + bro);
            ldmx2(bl[an], wbase_lo + nbase + bro);
        }
        const uint32_t aro = (uint32_t)((lid & 15) * 144 + (kk + ((lid & 16) ? 8 : 0)) * 2);
        #pragma unroll
        for (int am = 0; am < 4; am++) {
            uint32_t mbase = (uint32_t)((warp_row * 64 + am * 16) * 144);
            uint32_t ah4[4], al4[4];
            ldmx4(ah4, abase_hi + mbase + aro);
            ldmx4(al4, abase_lo + mbase + aro);
            #pragma unroll
            for (int an = 0; an < 4; an++) {
                mma16816(acc[am][an], ah4, bh[an]);
                mma16816(acc[am][an], ah4, bl[an]);
                mma16816(acc[am][an], al4, bh[an]);
            }
        }
    }
}

// ---------- weight transpose + bf16 hi/lo split: out[n*K+k] = W[k*N+n] ----------
__global__ void convsplit_k(const float* __restrict__ W,
                            __nv_bfloat16* __restrict__ hi, __nv_bfloat16* __restrict__ lo,
                            int K, int N)
{
    __shared__ float t[32][33];
    int kb = blockIdx.x * 32, nb = blockIdx.y * 32;
    int tx = threadIdx.x, ty = threadIdx.y;   // 32x8
    #pragma unroll
    for (int i = 0; i < 4; i++)
        t[ty + 8 * i][tx] = W[(size_t)(kb + ty + 8 * i) * N + nb + tx];
    __syncthreads();
    #pragma unroll
    for (int i = 0; i < 4; i++) {
        float v = t[tx][ty + 8 * i];
        __nv_bfloat16 h = __float2bfloat16(v);
        size_t oi = (size_t)(nb + ty + 8 * i) * K + kb + tx;
        hi[oi] = h;
        lo[oi] = __float2bfloat16(v - __bfloat162float(h));
    }
}

__global__ void zero_k(float* __restrict__ p, int n)
{
    int i = blockIdx.x * blockDim.x + threadIdx.x;
    if (i < n) p[i] = 0.f;
}
__global__ void copy_k(float* __restrict__ dst, const float* __restrict__ src, int n)
{
    int i = blockIdx.x * blockDim.x + threadIdx.x;
    if (i < n) dst[i] = src[i];
}
__global__ void bias_relu_k(float* __restrict__ C, const float* __restrict__ bias, int M, int N)
{
    int i = blockIdx.x * blockDim.x + threadIdx.x;
    if (i < M * N) C[i] = fmaxf(C[i] + bias[i % N], 0.f);
}

// ================= generic MMA GEMM =================
// C[M,N] (+)= A[M,K] @ B  where B pre-split transposed [N][K] bf16 hi/lo.
// grid: (N/128, ceil(M/128), nk); kslice = K/nk (multiple of 64).
#define GM_AHI 0
#define GM_ALO 18432
#define GM_WHI 36864
#define GM_WLO 55296
#define GM_SMEM 73728

__global__ void __launch_bounds__(256)
mma_gemm_k(const float* __restrict__ A,
           const __nv_bfloat16* __restrict__ Bhi, const __nv_bfloat16* __restrict__ Blo,
           const float* __restrict__ bias, float* __restrict__ C,
           int M, int N, int K, int kslice, int flags)
{
    extern __shared__ char smem[];
    uint32_t sb = smem_u32(smem);
    const int tid = threadIdx.x;
    const int wid = tid >> 5, lid = tid & 31;
    const int col0 = blockIdx.x * 128;
    const int row0 = blockIdx.y * 128;
    const int kstart = blockIdx.z * kslice;
    const int warp_row = wid >> 2, warp_col = wid & 3;

    const int r = tid >> 1, kh = tid & 1;
    int arow = row0 + r; if (arow >= M) arow = M - 1;
    const float* agp = A + (size_t)arow * K + kh * 32;
    const __nv_bfloat16* whp = Bhi + (size_t)(col0 + r) * K + kh * 32;
    const __nv_bfloat16* wlp = Blo + (size_t)(col0 + r) * K + kh * 32;
    const uint32_t soff = (uint32_t)(r * 144 + kh * 64);

    float acc[4][4][4];
    #pragma unroll
    for (int i = 0; i < 4; i++)
        #pragma unroll
        for (int j = 0; j < 4; j++)
            #pragma unroll
            for (int q = 0; q < 4; q++) acc[i][j][q] = 0.f;

    const int nchunk = kslice >> 6;
    for (int c = 0; c < nchunk; c++) {
        const int k0 = kstart + c * 64;
        __syncthreads();
        // W via cp.async
        #pragma unroll
        for (int j = 0; j < 4; j++) {
            cpasync16(sb + GM_WHI + soff + j * 16, whp + k0 + j * 8);
            cpasync16(sb + GM_WLO + soff + j * 16, wlp + k0 + j * 8);
        }
        CP_COMMIT();
        // A: load fp32, split hi/lo
        const float4* p = (const float4*)(agp + k0);
        #pragma unroll
        for (int j = 0; j < 8; j++) {
            float4 a = p[j];
            __nv_bfloat16 h0 = __float2bfloat16(a.x), h1 = __float2bfloat16(a.y);
            __nv_bfloat16 h2 = __float2bfloat16(a.z), h3 = __float2bfloat16(a.w);
            __nv_bfloat162 hw0 = __nv_bfloat162(h0, h1), hw1 = __nv_bfloat162(h2, h3);
            __nv_bfloat162 lw0 = __nv_bfloat162(__float2bfloat16(a.x - __bfloat162float(h0)),
                                                __float2bfloat16(a.y - __bfloat162float(h1)));
            __nv_bfloat162 lw1 = __nv_bfloat162(__float2bfloat16(a.z - __bfloat162float(h2)),
                                                __float2bfloat16(a.w - __bfloat162float(h3)));
            *(uint2*)(smem + GM_AHI + soff + j * 8) = make_uint2(*(uint32_t*)&hw0, *(uint32_t*)&hw1);
            *(uint2*)(smem + GM_ALO + soff + j * 8) = make_uint2(*(uint32_t*)&lw0, *(uint32_t*)&lw1);
        }
        CP_WAIT0();
        __syncthreads();
        mma_chunk(sb + GM_AHI, sb + GM_ALO, sb + GM_WHI, sb + GM_WLO,
                  acc, lid, warp_row, warp_col);
    }

    // epilogue
    #pragma unroll
    for (int am = 0; am < 4; am++) {
        #pragma unroll
        for (int q = 0; q < 4; q++) {
            int row = row0 + warp_row * 64 + am * 16 + (lid >> 2) + ((q >= 2) ? 8 : 0);
            if (row >= M) continue;
            #pragma unroll
            for (int an = 0; an < 4; an++) {
                int col = col0 + warp_col * 32 + an * 8 + (lid & 3) * 2 + (q & 1);
                size_t idx = (size_t)row * N + col;
                float v = acc[am][an][q];
                if (flags & FLAG_ATOMIC) {
                    atomicAdd(C + idx, v);
                } else {
                    if (bias) v += bias[col];
                    if (flags & FLAG_ACC) v += C[idx];
                    if (flags & FLAG_RELU) v = fmaxf(v, 0.f);
                    C[idx] = v;
                }
            }
        }
    }
}

// ================= pipelined pair MMA =================
// D = relu(Ah[h]+Ao[n]) @ W_a2 (hi/lo), epilogue adjp[row] += relu(D+b2).w3
#define PP_AHS   0
#define PP_ST0   8192
#define PP_STAGE 73728
#define PP_AHI 0
#define PP_ALO 18432
#define PP_WHI 36864
#define PP_WLO 55296
#define PP_RED 155648
#define PP_B2  156160
#define PP_W3  156672
#define PP_SMEM 157184

__global__ void __launch_bounds__(256)
pair_mma_k(const float* __restrict__ Ah, const float* __restrict__ Ao,
           const __nv_bfloat16* __restrict__ Wthi, const __nv_bfloat16* __restrict__ Wtlo,
           const float* __restrict__ b2, const float* __restrict__ w3,
           float* __restrict__ adjp)
{
    extern __shared__ char smem[];
    uint32_t sb = smem_u32(smem);
    const int tid = threadIdx.x;
    const int wid = tid >> 5, lid = tid & 31;
    const int col0 = blockIdx.x * 128;
    const int row0 = blockIdx.y * 128;
    const int h = row0 >> 8;
    const int nb = row0 & 255;
    const int warp_row = wid >> 2, warp_col = wid & 3;

    float* ahs = (float*)(smem + PP_AHS);
    if (tid < 128) {
        *(float*)(smem + PP_B2 + tid * 4) = b2[col0 + tid];
        *(float*)(smem + PP_W3 + tid * 4) = w3[col0 + tid];
        *(float*)(smem + PP_RED + tid * 4) = 0.f;
    }
    #pragma unroll
    for (int j = 0; j < 8; j++) ahs[tid + j * 256] = Ah[h * 2048 + tid + j * 256];
    __syncthreads();

    const int r = tid >> 1, kh = tid & 1;
    const float* aop = Ao + (size_t)(nb + r) * 2048 + kh * 32;
    const __nv_bfloat16* whp = Wthi + (size_t)(col0 + r) * 2048 + kh * 32;
    const __nv_bfloat16* wlp = Wtlo + (size_t)(col0 + r) * 2048 + kh * 32;
    const uint32_t soff = (uint32_t)(r * 144 + kh * 64);

    float acc[4][4][4];
    #pragma unroll
    for (int i = 0; i < 4; i++)
        #pragma unroll
        for (int j = 0; j < 4; j++)
            #pragma unroll
            for (int q = 0; q < 4; q++) acc[i][j][q] = 0.f;

    float4 pa[8];

    // ---- prologue: chunk 0 into stage 0 ----
    {
        uint32_t stb = sb + PP_ST0;
        #pragma unroll
        for (int j = 0; j < 4; j++) {
            cpasync16(stb + PP_WHI + soff + j * 16, whp + j * 8);
            cpasync16(stb + PP_WLO + soff + j * 16, wlp + j * 8);
        }
        CP_COMMIT();
        const float4* p = (const float4*)aop;
        #pragma unroll
        for (int j = 0; j < 8; j++) pa[j] = p[j];
        char* stc = smem + PP_ST0;
        const float* ah = ahs + kh * 32;
        #pragma unroll
        for (int j = 0; j < 8; j++) {
            float v0 = fmaxf(pa[j].x + ah[j * 4 + 0], 0.f);
            float v1 = fmaxf(pa[j].y + ah[j * 4 + 1], 0.f);
            float v2 = fmaxf(pa[j].z + ah[j * 4 + 2], 0.f);
            float v3 = fmaxf(pa[j].w + ah[j * 4 + 3], 0.f);
            __nv_bfloat16 h0 = __float2bfloat16(v0), h1 = __float2bfloat16(v1);
            __nv_bfloat16 h2 = __float2bfloat16(v2), h3 = __float2bfloat16(v3);
            __nv_bfloat162 hw0 = __nv_bfloat162(h0, h1), hw1 = __nv_bfloat162(h2, h3);
            __nv_bfloat162 lw0 = __nv_bfloat162(__float2bfloat16(v0 - __bfloat162float(h0)),
                                                __float2bfloat16(v1 - __bfloat162float(h1)));
            __nv_bfloat162 lw1 = __nv_bfloat162(__float2bfloat16(v2 - __bfloat162float(h2)),
                                                __float2bfloat16(v3 - __bfloat162float(h3)));
            *(uint2*)(stc + PP_AHI + soff + j * 8) = make_uint2(*(uint32_t*)&hw0, *(uint32_t*)&hw1);
            *(uint2*)(stc + PP_ALO + soff + j * 8) = make_uint2(*(uint32_t*)&lw0, *(uint32_t*)&lw1);
        }
    }

    // ---- main pipelined loop ----
    for (int c = 0; c < 32; c++) {
        const int cur = c & 1;
        CP_WAIT0();
        __syncthreads();
        if (c < 31) {
            // fire W cp.async for next chunk, prefetch Ao into regs
            uint32_t stb = sb + PP_ST0 + (cur ^ 1) * PP_STAGE;
            const int kn = (c + 1) * 64;
            #pragma unroll
            for (int j = 0; j < 4; j++) {
                cpasync16(stb + PP_WHI + soff + j * 16, whp + kn + j * 8);
                cpasync16(stb + PP_WLO + soff + j * 16, wlp + kn + j * 8);
            }
            CP_COMMIT();
            const float4* p = (const float4*)(aop + kn);
            #pragma unroll
            for (int j = 0; j < 8; j++) pa[j] = p[j];
        }
        uint32_t stb = sb + PP_ST0 + cur * PP_STAGE;
        mma_chunk(stb + PP_AHI, stb + PP_ALO, stb + PP_WHI, stb + PP_WLO,
                  acc, lid, warp_row, warp_col);
        if (c < 31) {
            // convert + store next A chunk (data prefetched above)
            char* stc = smem + PP_ST0 + (cur ^ 1) * PP_STAGE;
            const float* ah = ahs + (c + 1) * 64 + kh * 32;
            #pragma unroll
            for (int j = 0; j < 8; j++) {
                float v0 = fmaxf(pa[j].x + ah[j * 4 + 0], 0.f);
                float v1 = fmaxf(pa[j].y + ah[j * 4 + 1], 0.f);
                float v2 = fmaxf(pa[j].z + ah[j * 4 + 2], 0.f);
                float v3 = fmaxf(pa[j].w + ah[j * 4 + 3], 0.f);
                __nv_bfloat16 h0 = __float2bfloat16(v0), h1 = __float2bfloat16(v1);
                __nv_bfloat16 h2 = __float2bfloat16(v2), h3 = __float2bfloat16(v3);
                __nv_bfloat162 hw0 = __nv_bfloat162(h0, h1), hw1 = __nv_bfloat162(h2, h3);
                __nv_bfloat162 lw0 = __nv_bfloat162(__float2bfloat16(v0 - __bfloat162float(h0)),
                                                    __float2bfloat16(v1 - __bfloat162float(h1)));
                __nv_bfloat162 lw1 = __nv_bfloat162(__float2bfloat16(v2 - __bfloat162float(h2)),
                                                    __float2bfloat16(v3 - __bfloat162float(h3)));
                *(uint2*)(stc + PP_AHI + soff + j * 8) = make_uint2(*(uint32_t*)&hw0, *(uint32_t*)&hw1);
                *(uint2*)(stc + PP_ALO + soff + j * 8) = make_uint2(*(uint32_t*)&lw0, *(uint32_t*)&lw1);
            }
        }
    }

    // ---- fused epilogue: adjp[row] += relu(D + b2) . w3 ----
    const float* b2s = (const float*)(smem + PP_B2);
    const float* w3s = (const float*)(smem + PP_W3);
    float* sred = (float*)(smem + PP_RED);
    #pragma unroll
    for (int am = 0; am < 4; am++) {
        float pl = 0.f, ph = 0.f;
        #pragma unroll
        for (int an = 0; an < 4; an++) {
            int cb = warp_col * 32 + an * 8 + 2 * (lid & 3);
            float w0 = w3s[cb], w1 = w3s[cb + 1];
            float bb0 = b2s[cb], bb1 = b2s[cb + 1];
            pl += fmaxf(acc[am][an][0] + bb0, 0.f) * w0 + fmaxf(acc[am][an][1] + bb1, 0.f) * w1;
            ph += fmaxf(acc[am][an][2] + bb0, 0.f) * w0 + fmaxf(acc[am][an][3] + bb1, 0.f) * w1;
        }
        pl += __shfl_xor_sync(0xffffffffu, pl, 1);
        pl += __shfl_xor_sync(0xffffffffu, pl, 2);
        ph += __shfl_xor_sync(0xffffffffu, ph, 1);
        ph += __shfl_xor_sync(0xffffffffu, ph, 2);
        if ((lid & 3) == 0) {
            int rloc = warp_row * 64 + am * 16 + (lid >> 2);
            atomicAdd(sred + rloc, pl);
            atomicAdd(sred + rloc + 8, ph);
        }
    }
    __syncthreads();
    if (tid < 128) atomicAdd(adjp + row0 + tid, sred[tid]);
}

// ---------------- adj = sigmoid(adjp + b_a3) ----------------
__global__ void adjfin_k(const float* __restrict__ adjp, const float* __restrict__ b3,
                         float* __restrict__ adj)
{
    int p = blockIdx.x * 256 + threadIdx.x;
    if (p < NPAIR) adj[p] = 1.f / (1.f + expf(-(adjp[p] + b3[0])));
}

// ---------------- agg_o[h,e] ----------------
__global__ void aggo_k(const float* __restrict__ adj, const float* __restrict__ obj,
                       const float* __restrict__ nssa, float* __restrict__ out)
{
    int h = blockIdx.y;
    int e = blockIdx.x * 128 + threadIdx.x;
    __shared__ float sa[256];
    for (int i = threadIdx.x; i < 256; i += 128) sa[i] = adj[h * 256 + i];
    __syncthreads();
    float a1 = 0.f, a2 = 0.f;
    #pragma unroll 4
    for (int n = 0; n < 256; n++) {
        float a = sa[n];
        float om = obj[n * 1024 + e];
        float ns = nssa[n * 1024 + e];
        a1 += a * om;
        a2 += a * om * ns;
    }
    out[h * 1024 + e] = nssa[h * 1024 + e] * a1 - a2;
}

// ---------------- agg_h[n,e] ----------------
__global__ void aggh_k(const float* __restrict__ adj, const float* __restrict__ hum,
                       const float* __restrict__ nssa, float* __restrict__ out)
{
    int n = blockIdx.y;
    int e = blockIdx.x * 128 + threadIdx.x;
    __shared__ float sa[64];
    if (threadIdx.x < 64) sa[threadIdx.x] = adj[threadIdx.x * 256 + n];
    __syncthreads();
    float a1 = 0.f, a2 = 0.f;
    #pragma unroll 4
    for (int h = 0; h < 64; h++) {
        float a = sa[h];
        float hm = hum[h * 1024 + e];
        float hs = nssa[h * 1024 + e];
        a1 += a * hm;
        a2 += a * hm * hs;
    }
    out[n * 1024 + e] = nssa[n * 1024 + e] * a1 - a2;
}

// ---------------- mask dtype detect ----------------
__global__ void detect_k(const unsigned char* __restrict__ cm)
{
    __shared__ int s_f, s_nz;
    if (threadIdx.x == 0) { s_f = 0; s_nz = 0; }
    __syncthreads();
    int lf = 0, lnz = 0;
    for (int i = threadIdx.x; i < 9360; i += blockDim.x) {
        unsigned char b = cm[i];
        int m4 = i & 3;
        if (m4 == 3 && b == 0x3F) lf = 1;
        if (m4 != 0 && b != 0) lnz = 1;
    }
    if (lf) atomicOr(&s_f, 1);
    if (lnz) atomicOr(&s_nz, 1);
    __syncthreads();
    if (threadIdx.x == 0) g_mask_mode = s_f ? 2 : (s_nz ? 0 : 1);
}

__device__ __forceinline__ float lisf(float x)
{
    return 8.3f / (1.f + expf(12.f - 10.f * x));
}

// ---------------- final gather ----------------
__global__ void out_k(const float* __restrict__ hfin, const float* __restrict__ efin,
                      const float* __restrict__ nsp, const float* __restrict__ adj,
                      const float* __restrict__ scores, const int* __restrict__ labels,
                      const void* __restrict__ cmask, float* __restrict__ out)
{
    int p = blockIdx.x;
    int x = p / 255;
    int r = p % 255;
    int y = (r < x) ? r : r + 1;

    float scale = adj[x * 256 + y] * lisf(scores[x]) * lisf(scores[y]);
    int lab = labels[y];
    int mode = g_mask_mode;

    const float* hx = hfin + x * 1024;
    const float* sx = nsp + x * 1024;
    const float* ey = efin + y * 1024;
    const float* ny = nsp + y * 1024;
    float* o = out + (size_t)p * OUTC;

    for (int c = threadIdx.x; c < OUTC; c += blockDim.x) {
        float v;
        if (c < 1024)       v = hx[c];
        else if (c < 2048)  v = sx[c - 1024];
        else if (c < 3072)  v = ey[c - 2048];
        else if (c < 4096)  v = ny[c - 3072];
        else {
            int j = c - 4096;
            float m;
            if (mode == 0)      m = ((const unsigned char*)cmask)[lab * NCLS + j] ? 1.f : 0.f;
            else if (mode == 1) m = ((const int*)cmask)[lab * NCLS + j] ? 1.f : 0.f;
            else                m = ((const float*)cmask)[lab * NCLS + j];
            v = scale * m;
        }
        o[c] = v;
    }
}

// ---------------- host ----------------
static inline void launch_mma(const float* A, const __nv_bfloat16* Bhi, const __nv_bfloat16* Blo,
                              const float* bias, float* C, int M, int N, int K,
                              int nk, int flags)
{
    dim3 grid(N / 128, (M + 127) / 128, nk);
    mma_gemm_k<<<grid, 256, GM_SMEM>>>(A, Bhi, Blo, bias, C, M, N, K, K / nk, flags);
}

extern "C" void kernel_launch(void* const* d_in, const int* in_sizes, int n_in,
                              void* d_out, int out_size)
{
    const float *box = 0, *nsp = 0, *scores = 0;
    const int *labels = 0;
    const void *cmask = 0;
    const float *W_bh1 = 0, *b_bh1 = 0, *W_bh2 = 0, *b_bh2 = 0, *W_sa = 0;
    const float *W_a1 = 0, *b_a1 = 0, *W_a2 = 0, *b_a2 = 0, *W_a3 = 0, *b_a3 = 0;
    const float *W_hm = 0, *b_hm = 0, *W_om = 0, *b_om = 0, *W_hu = 0, *W_ou = 0;

    int c256 = 0, c1k = 0, c1m = 0, c2m = 0;
    for (int i = 0; i < n_in; i++) {
        const void* p = d_in[i];
        switch (in_sizes[i]) {
            case 3211264:  box = (const float*)p; break;
            case 262144:   nsp = (const float*)p; break;
            case 256:      if (c256++ == 0) scores = (const float*)p; else labels = (const int*)p; break;
            case 9360:     cmask = p; break;
            case 12845056: W_bh1 = (const float*)p; break;
            case 1024:
                switch (c1k++) {
                    case 0: b_bh1 = (const float*)p; break;
                    case 1: b_bh2 = (const float*)p; break;
                    case 2: b_a2  = (const float*)p; break;
                    case 3: W_a3  = (const float*)p; break;
                    case 4: b_hm  = (const float*)p; break;
                    case 5: b_om  = (const float*)p; break;
                } break;
            case 1048576:
                switch (c1m++) {
                    case 0: W_bh2 = (const float*)p; break;
                    case 1: W_sa  = (const float*)p; break;
                    case 2: W_hm  = (const float*)p; break;
                    case 3: W_om  = (const float*)p; break;
                } break;
            case 8388608:  W_a1 = (const float*)p; break;
            case 2048:     b_a1 = (const float*)p; break;
            case 2097152:
                switch (c2m++) {
                    case 0: W_a2 = (const float*)p; break;
                    case 1: W_hu = (const float*)p; break;
                    case 2: W_ou = (const float*)p; break;
                } break;
            case 1:        b_a3 = (const float*)p; break;
            default: break;
        }
    }

    float *enc1, *encA, *encB, *hA, *hB, *nssa, *Ah, *Ao, *adjp, *adj, *obj, *hum, *aggo, *aggh;
    cudaGetSymbolAddress((void**)&enc1, g_enc1);
    cudaGetSymbolAddress((void**)&encA, g_encA);
    cudaGetSymbolAddress((void**)&encB, g_encB);
    cudaGetSymbolAddress((void**)&hA,   g_hA);
    cudaGetSymbolAddress((void**)&hB,   g_hB);
    cudaGetSymbolAddress((void**)&nssa, g_nssa);
    cudaGetSymbolAddress((void**)&Ah,   g_Ah);
    cudaGetSymbolAddress((void**)&Ao,   g_Ao);
    cudaGetSymbolAddress((void**)&adjp, g_adjp);
    cudaGetSymbolAddress((void**)&adj,  g_adj);
    cudaGetSymbolAddress((void**)&obj,  g_obj);
    cudaGetSymbolAddress((void**)&hum,  g_hum);
    cudaGetSymbolAddress((void**)&aggo, g_aggo);
    cudaGetSymbolAddress((void**)&aggh, g_aggh);

    __nv_bfloat16 *bh1hi, *bh1lo, *bh2hi, *bh2lo, *sahi, *salo, *omhi, *omlo, *hmhi, *hmlo;
    __nv_bfloat16 *a2hi, *a2lo, *a1hi, *a1lo, *huhi, *hulo, *ouhi, *oulo;
    cudaGetSymbolAddress((void**)&bh1hi, g_bh1hi);
    cudaGetSymbolAddress((void**)&bh1lo, g_bh1lo);
    cudaGetSymbolAddress((void**)&bh2hi, g_bh2hi);
    cudaGetSymbolAddress((void**)&bh2lo, g_bh2lo);
    cudaGetSymbolAddress((void**)&sahi,  g_sahi);
    cudaGetSymbolAddress((void**)&salo,  g_salo);
    cudaGetSymbolAddress((void**)&omhi,  g_omhi);
    cudaGetSymbolAddress((void**)&omlo,  g_omlo);
    cudaGetSymbolAddress((void**)&hmhi,  g_hmhi);
    cudaGetSymbolAddress((void**)&hmlo,  g_hmlo);
    cudaGetSymbolAddress((void**)&a2hi,  g_a2hi);
    cudaGetSymbolAddress((void**)&a2lo,  g_a2lo);
    cudaGetSymbolAddress((void**)&a1hi,  g_a1hi);
    cudaGetSymbolAddress((void**)&a1lo,  g_a1lo);
    cudaGetSymbolAddress((void**)&huhi,  g_huhi);
    cudaGetSymbolAddress((void**)&hulo,  g_hulo);
    cudaGetSymbolAddress((void**)&ouhi,  g_ouhi);
    cudaGetSymbolAddress((void**)&oulo,  g_oulo);

    cudaFuncSetAttribute(pair_mma_k, cudaFuncAttributeMaxDynamicSharedMemorySize, PP_SMEM);
    cudaFuncSetAttribute(mma_gemm_k, cudaFuncAttributeMaxDynamicSharedMemorySize, GM_SMEM);

    dim3 cb(32, 8);
    // ---- weight transpose + split (once per launch) ----
    convsplit_k<<<dim3(392, 32), cb>>>(W_bh1, bh1hi, bh1lo, 12544, 1024);
    convsplit_k<<<dim3(32, 32), cb>>>(W_bh2, bh2hi, bh2lo, 1024, 1024);
    convsplit_k<<<dim3(32, 32), cb>>>(W_sa,  sahi,  salo,  1024, 1024);
    convsplit_k<<<dim3(32, 32), cb>>>(W_om,  omhi,  omlo,  1024, 1024);
    convsplit_k<<<dim3(32, 32), cb>>>(W_hm,  hmhi,  hmlo,  1024, 1024);
    convsplit_k<<<dim3(64, 32), cb>>>(W_a2,  a2hi,  a2lo,  2048, 1024);
    for (int s = 0; s < 4; s++)
        convsplit_k<<<dim3(32, 64), cb>>>(W_a1 + (size_t)s * 1024 * 2048,
                                          a1hi + (size_t)s * 2048 * 1024,
                                          a1lo + (size_t)s * 2048 * 1024, 1024, 2048);
    for (int s = 0; s < 2; s++) {
        convsplit_k<<<dim3(32, 32), cb>>>(W_hu + (size_t)s * 1024 * 1024,
                                          huhi + (size_t)s * 1024 * 1024,
                                          hulo + (size_t)s * 1024 * 1024, 1024, 1024);
        convsplit_k<<<dim3(32, 32), cb>>>(W_ou + (size_t)s * 1024 * 1024,
                                          ouhi + (size_t)s * 1024 * 1024,
                                          oulo + (size_t)s * 1024 * 1024, 1024, 1024);
    }

    // ---- encoder ----
    zero_k<<<NOBJ * EDIM / 256, 256>>>(enc1, NOBJ * EDIM);
    launch_mma(box, bh1hi, bh1lo, 0, enc1, NOBJ, 1024, 12544, 7, FLAG_ATOMIC);
    bias_relu_k<<<NOBJ * EDIM / 256, 256>>>(enc1, b_bh1, NOBJ, 1024);
    launch_mma(enc1, bh2hi, bh2lo, b_bh2, encA, NOBJ, 1024, 1024, 1, FLAG_RELU);
    launch_mma(nsp,  sahi,  salo,  0,     nssa, NOBJ, 1024, 1024, 1, 0);
    copy_k<<<(NHUM * EDIM + 255) / 256, 256>>>(hA, encA, NHUM * EDIM);

    float* enc_in = encA;  float* enc_out = encB;
    float* h_in = hA;      float* h_out = hB;

    for (int it = 0; it < 2; it++) {
        // A_h = h_enc @ Wa1[0:1024] + h_sp @ Wa1[1024:2048] + b_a1
        launch_mma(h_in, a1hi, a1lo, 0, Ah, NHUM, 2048, 1024, 1, 0);
        launch_mma(nsp, a1hi + (size_t)1 * 2048 * 1024, a1lo + (size_t)1 * 2048 * 1024,
                   b_a1, Ah, NHUM, 2048, 1024, 1, FLAG_ACC);
        // A_o = enc @ Wa1[2048:3072] + nsp @ Wa1[3072:4096]
        launch_mma(enc_in, a1hi + (size_t)2 * 2048 * 1024, a1lo + (size_t)2 * 2048 * 1024,
                   0, Ao, NOBJ, 2048, 1024, 1, 0);
        launch_mma(nsp, a1hi + (size_t)3 * 2048 * 1024, a1lo + (size_t)3 * 2048 * 1024,
                   0, Ao, NOBJ, 2048, 1024, 1, FLAG_ACC);

        // adj pre-activation (fused pair GEMM; hdn2 never materialized)
        zero_k<<<NPAIR / 256, 256>>>(adjp, NPAIR);
        pair_mma_k<<<dim3(8, 128), 256, PP_SMEM>>>(Ah, Ao, a2hi, a2lo, b_a2, W_a3, adjp);
        adjfin_k<<<NPAIR / 256, 256>>>(adjp, b_a3, adj);

        // obj_msg, agg_o
        launch_mma(enc_in, omhi, omlo, b_om, obj, NOBJ, 1024, 1024, 1, FLAG_RELU);
        aggo_k<<<dim3(8, NHUM), 128>>>(adj, obj, nssa, aggo);

        // h_enc = [h_enc | agg_o] @ W_hu
        launch_mma(h_in, huhi, hulo, 0, h_out, NHUM, 1024, 1024, 1, 0);
        launch_mma(aggo, huhi + (size_t)1024 * 1024, hulo + (size_t)1024 * 1024,
                   0, h_out, NHUM, 1024, 1024, 1, FLAG_ACC);

        // hum_msg, agg_h
        launch_mma(h_out, hmhi, hmlo, b_hm, hum, NHUM, 1024, 1024, 1, FLAG_RELU);
        aggh_k<<<dim3(8, NOBJ), 128>>>(adj, hum, nssa, aggh);

        // enc = [enc | agg_h] @ W_ou
        launch_mma(enc_in, ouhi, oulo, 0, enc_out, NOBJ, 1024, 1024, 1, 0);
        launch_mma(aggh, ouhi + (size_t)1024 * 1024, oulo + (size_t)1024 * 1024,
                   0, enc_out, NOBJ, 1024, 1024, 1, FLAG_ACC);

        float* t;
        t = enc_in; enc_in = enc_out; enc_out = t;
        t = h_in;   h_in = h_out;     h_out = t;
    }

    // ---- final gather ----
    detect_k<<<1, 256>>>((const unsigned char*)cmask);
    out_k<<<NKEEP, 128>>>(h_in, enc_in, nsp, adj, scores, labels, cmask, (float*)d_out);
}

// round 6
// speedup vs baseline: 3.0244x; 1.3354x over previous
#include <cuda_runtime.h>
#include <cuda_bf16.h>
#include <cuda_fp16.h>
#include <math.h>
#include <stdint.h>

// ---------------- problem constants ----------------
#define NOBJ 256
#define NHUM 64
#define EDIM 1024
#define NPAIR 16384
#define NKEEP 16320
#define OUTC 4213
#define NCLS 117

#define FLAG_ACC    1
#define FLAG_RELU   2
#define FLAG_ATOMIC 4

// ---------------- scratch ----------------
__device__ float g_enc1[NOBJ*EDIM];
__device__ float g_nssa[NOBJ*EDIM];
__device__ float g_Ah[NHUM*2048];
__device__ float g_Ao[NOBJ*2048];
__device__ float g_adjp[NPAIR];
__device__ float g_adj[NPAIR];
__device__ float g_obj[NOBJ*EDIM];
__device__ float g_hum[NHUM*EDIM];
__device__ float g_hf[NHUM*2048];     // [h_enc | h_sp]
__device__ float g_hcat[NHUM*2048];   // [h_enc | agg_o]
__device__ float g_of[NOBJ*2048];     // [enc | nsp]
__device__ float g_ocat[NOBJ*2048];   // [enc | agg_h]
__device__ int   g_mask_mode;

// pre-split transposed weights [n][k]
__device__ __nv_bfloat16 g_bh1hi[1024*12544];
__device__ __nv_bfloat16 g_bh1lo[1024*12544];
__device__ __nv_bfloat16 g_bh2hi[1024*1024];
__device__ __nv_bfloat16 g_bh2lo[1024*1024];
__device__ __nv_bfloat16 g_sahi[1024*1024];
__device__ __nv_bfloat16 g_salo[1024*1024];
__device__ __nv_bfloat16 g_omhi[1024*1024];
__device__ __nv_bfloat16 g_omlo[1024*1024];
__device__ __nv_bfloat16 g_hmhi[1024*1024];
__device__ __nv_bfloat16 g_hmlo[1024*1024];
__device__ __nv_bfloat16 g_a1hi[2*2048*2048];
__device__ __nv_bfloat16 g_a1lo[2*2048*2048];
__device__ __nv_bfloat16 g_huhi[1024*2048];
__device__ __nv_bfloat16 g_hulo[1024*2048];
__device__ __nv_bfloat16 g_ouhi[1024*2048];
__device__ __nv_bfloat16 g_oulo[1024*2048];
__device__ __half        g_a2h[1024*2048];   // W_a2^T fp16 single

__device__ __forceinline__ uint32_t smem_u32(const void* p) {
    uint32_t a;
    asm("{ .reg .u64 t; cvta.to.shared.u64 t, %1; cvt.u32.u64 %0, t; }" : "=r"(a) : "l"(p));
    return a;
}
__device__ __forceinline__ void cpasync16(uint32_t saddr, const void* g) {
    asm volatile("{ .reg .u64 gg; cvta.to.global.u64 gg, %1; "
                 "cp.async.cg.shared.global [%0], [gg], 16; }"
                 :: "r"(saddr), "l"(g));
}
#define CP_COMMIT() asm volatile("cp.async.commit_group;")
#define CP_WAIT0()  asm volatile("cp.async.wait_group 0;")

// ================= mma.sync helpers =================
__device__ __forceinline__ void mma_bf16(float* c, const uint32_t* a, const uint32_t* b)
{
    asm volatile("mma.sync.aligned.m16n8k16.row.col.f32.bf16.bf16.f32 "
                 "{%0,%1,%2,%3}, {%4,%5,%6,%7}, {%8,%9}, {%0,%1,%2,%3};"
                 : "+f"(c[0]), "+f"(c[1]), "+f"(c[2]), "+f"(c[3])
                 : "r"(a[0]), "r"(a[1]), "r"(a[2]), "r"(a[3]), "r"(b[0]), "r"(b[1]));
}
__device__ __forceinline__ void mma_f16(float* c, const uint32_t* a, const uint32_t* b)
{
    asm volatile("mma.sync.aligned.m16n8k16.row.col.f32.f16.f16.f32 "
                 "{%0,%1,%2,%3}, {%4,%5,%6,%7}, {%8,%9}, {%0,%1,%2,%3};"
                 : "+f"(c[0]), "+f"(c[1]), "+f"(c[2]), "+f"(c[3])
                 : "r"(a[0]), "r"(a[1]), "r"(a[2]), "r"(a[3]), "r"(b[0]), "r"(b[1]));
}
__device__ __forceinline__ void ldmx4(uint32_t* d, uint32_t addr)
{
    asm volatile("ldmatrix.sync.aligned.m8n8.x4.shared.b16 {%0,%1,%2,%3}, [%4];"
                 : "=r"(d[0]), "=r"(d[1]), "=r"(d[2]), "=r"(d[3]) : "r"(addr));
}
__device__ __forceinline__ void ldmx2(uint32_t* d, uint32_t addr)
{
    asm volatile("ldmatrix.sync.aligned.m8n8.x2.shared.b16 {%0,%1}, [%2];"
                 : "=r"(d[0]), "=r"(d[1]) : "r"(addr));
}

// bf16 hi/lo 3-pass chunk (feature GEMMs): 128x128 tile, K=64, stride 144B
__device__ __forceinline__ void mma_chunk(uint32_t abase_hi, uint32_t abase_lo,
                                          uint32_t wbase_hi, uint32_t wbase_lo,
                                          float acc[4][4][4], int lid,
                                          int warp_row, int warp_col)
{
    #pragma unroll
    for (int ks = 0; ks < 4; ks++) {
        const int kk = ks * 16;
        uint32_t bh[4][2], bl[4][2];
        const int l2 = lid & 15;
        const uint32_t bro = (uint32_t)((l2 & 7) * 144 + (kk + ((l2 & 8) ? 8 : 0)) * 2);
        #pragma unroll
        for (int an = 0; an < 4; an++) {
            uint32_t nbase = (uint32_t)((warp_col * 32 + an * 8) * 144);
            ldmx2(bh[an], wbase_hi + nbase + bro);
            ldmx2(bl[an], wbase_lo + nbase + bro);
        }
        const uint32_t aro = (uint32_t)((lid & 15) * 144 + (kk + ((lid & 16) ? 8 : 0)) * 2);
        #pragma unroll
        for (int am = 0; am < 4; am++) {
            uint32_t mbase = (uint32_t)((warp_row * 64 + am * 16) * 144);
            uint32_t ah4[4], al4[4];
            ldmx4(ah4, abase_hi + mbase + aro);
            ldmx4(al4, abase_lo + mbase + aro);
            #pragma unroll
            for (int an = 0; an < 4; an++) {
                mma_bf16(acc[am][an], ah4, bh[an]);
                mma_bf16(acc[am][an], ah4, bl[an]);
                mma_bf16(acc[am][an], al4, bh[an]);
            }
        }
    }
}

// fp16 single-pass chunk (pair GEMM)
__device__ __forceinline__ void pair_chunk_f16(uint32_t abase, uint32_t wbase,
                                               float acc[4][4][4], int lid,
                                               int warp_row, int warp_col)
{
    const int n_off = ((lid >> 4) & 1) * 8 + (lid & 7);
    const int kb = ((lid >> 3) & 1) * 8;
    #pragma unroll
    for (int ks = 0; ks < 4; ks++) {
        const int kk = ks * 16;
        uint32_t b[4][2];
        #pragma unroll
        for (int anp = 0; anp < 2; anp++) {
            uint32_t t[4];
            uint32_t addr = wbase + (uint32_t)((warp_col * 32 + anp * 16 + n_off) * 144
                                               + (kk + kb) * 2);
            ldmx4(t, addr);
            b[anp * 2][0] = t[0]; b[anp * 2][1] = t[1];
            b[anp * 2 + 1][0] = t[2]; b[anp * 2 + 1][1] = t[3];
        }
        const uint32_t aro = (uint32_t)((lid & 15) * 144 + (kk + ((lid & 16) ? 8 : 0)) * 2);
        #pragma unroll
        for (int am = 0; am < 4; am++) {
            uint32_t a4[4];
            ldmx4(a4, abase + (uint32_t)((warp_row * 64 + am * 16) * 144) + aro);
            #pragma unroll
            for (int an = 0; an < 4; an++)
                mma_f16(acc[am][an], a4, b[an]);
        }
    }
}

// ---------- weight transpose + bf16 hi/lo split ----------
__global__ void convsplit_k(const float* __restrict__ W,
                            __nv_bfloat16* __restrict__ hi, __nv_bfloat16* __restrict__ lo,
                            int K, int N)
{
    __shared__ float t[32][33];
    int kb = blockIdx.x * 32, nb = blockIdx.y * 32;
    int tx = threadIdx.x, ty = threadIdx.y;
    #pragma unroll
    for (int i = 0; i < 4; i++)
        t[ty + 8 * i][tx] = W[(size_t)(kb + ty + 8 * i) * N + nb + tx];
    __syncthreads();
    #pragma unroll
    for (int i = 0; i < 4; i++) {
        float v = t[tx][ty + 8 * i];
        __nv_bfloat16 h = __float2bfloat16(v);
        size_t oi = (size_t)(nb + ty + 8 * i) * K + kb + tx;
        hi[oi] = h;
        lo[oi] = __float2bfloat16(v - __bfloat162float(h));
    }
}

// ---------- weight transpose + fp16 single ----------
__global__ void convf16_k(const float* __restrict__ W, __half* __restrict__ out,
                          int K, int N)
{
    __shared__ float t[32][33];
    int kb = blockIdx.x * 32, nb = blockIdx.y * 32;
    int tx = threadIdx.x, ty = threadIdx.y;
    #pragma unroll
    for (int i = 0; i < 4; i++)
        t[ty + 8 * i][tx] = W[(size_t)(kb + ty + 8 * i) * N + nb + tx];
    __syncthreads();
    #pragma unroll
    for (int i = 0; i < 4; i++)
        out[(size_t)(nb + ty + 8 * i) * K + kb + tx] = __float2half_rn(t[tx][ty + 8 * i]);
}

__global__ void zero_k(float* __restrict__ p, int n)
{
    int i = blockIdx.x * blockDim.x + threadIdx.x;
    if (i < n) p[i] = 0.f;
}
__global__ void copy2d_k(float* __restrict__ dst, int dls, const float* __restrict__ src,
                         int sls, int rows, int cols)
{
    int i = blockIdx.x * blockDim.x + threadIdx.x;
    if (i < rows * cols) {
        int r = i / cols, c = i % cols;
        dst[r * dls + c] = src[r * sls + c];
    }
}
__global__ void bias_relu_k(float* __restrict__ C, const float* __restrict__ bias, int M, int N)
{
    int i = blockIdx.x * blockDim.x + threadIdx.x;
    if (i < M * N) C[i] = fmaxf(C[i] + bias[i % N], 0.f);
}

// ================= generic MMA GEMM (bf16 hi/lo) with lda/ldc =================
#define GM_AHI 0
#define GM_ALO 18432
#define GM_WHI 36864
#define GM_WLO 55296
#define GM_SMEM 73728

__global__ void __launch_bounds__(256)
mma_gemm_k(const float* __restrict__ A, int lda,
           const __nv_bfloat16* __restrict__ Bhi, const __nv_bfloat16* __restrict__ Blo,
           const float* __restrict__ bias, float* __restrict__ C, int ldc,
           int M, int N, int K, int kslice, int flags)
{
    extern __shared__ char smem[];
    uint32_t sb = smem_u32(smem);
    const int tid = threadIdx.x;
    const int wid = tid >> 5, lid = tid & 31;
    const int col0 = blockIdx.x * 128;
    const int row0 = blockIdx.y * 128;
    const int kstart = blockIdx.z * kslice;
    const int warp_row = wid >> 2, warp_col = wid & 3;

    const int r = tid >> 1, kh = tid & 1;
    int arow = row0 + r; if (arow >= M) arow = M - 1;
    const float* agp = A + (size_t)arow * lda + kh * 32;
    const __nv_bfloat16* whp = Bhi + (size_t)(col0 + r) * K + kh * 32;
    const __nv_bfloat16* wlp = Blo + (size_t)(col0 + r) * K + kh * 32;
    const uint32_t soff = (uint32_t)(r * 144 + kh * 64);

    float acc[4][4][4];
    #pragma unroll
    for (int i = 0; i < 4; i++)
        #pragma unroll
        for (int j = 0; j < 4; j++)
            #pragma unroll
            for (int q = 0; q < 4; q++) acc[i][j][q] = 0.f;

    const int nchunk = kslice >> 6;
    for (int c = 0; c < nchunk; c++) {
        const int k0 = kstart + c * 64;
        __syncthreads();
        #pragma unroll
        for (int j = 0; j < 4; j++) {
            cpasync16(sb + GM_WHI + soff + j * 16, whp + k0 + j * 8);
            cpasync16(sb + GM_WLO + soff + j * 16, wlp + k0 + j * 8);
        }
        CP_COMMIT();
        const float4* p = (const float4*)(agp + k0);
        #pragma unroll
        for (int j = 0; j < 8; j++) {
            float4 a = p[j];
            __nv_bfloat16 h0 = __float2bfloat16(a.x), h1 = __float2bfloat16(a.y);
            __nv_bfloat16 h2 = __float2bfloat16(a.z), h3 = __float2bfloat16(a.w);
            __nv_bfloat162 hw0 = __nv_bfloat162(h0, h1), hw1 = __nv_bfloat162(h2, h3);
            __nv_bfloat162 lw0 = __nv_bfloat162(__float2bfloat16(a.x - __bfloat162float(h0)),
                                                __float2bfloat16(a.y - __bfloat162float(h1)));
            __nv_bfloat162 lw1 = __nv_bfloat162(__float2bfloat16(a.z - __bfloat162float(h2)),
                                                __float2bfloat16(a.w - __bfloat162float(h3)));
            *(uint2*)(smem + GM_AHI + soff + j * 8) = make_uint2(*(uint32_t*)&hw0, *(uint32_t*)&hw1);
            *(uint2*)(smem + GM_ALO + soff + j * 8) = make_uint2(*(uint32_t*)&lw0, *(uint32_t*)&lw1);
        }
        CP_WAIT0();
        __syncthreads();
        mma_chunk(sb + GM_AHI, sb + GM_ALO, sb + GM_WHI, sb + GM_WLO,
                  acc, lid, warp_row, warp_col);
    }

    #pragma unroll
    for (int am = 0; am < 4; am++) {
        #pragma unroll
        for (int q = 0; q < 4; q++) {
            int row = row0 + warp_row * 64 + am * 16 + (lid >> 2) + ((q >= 2) ? 8 : 0);
            if (row >= M) continue;
            #pragma unroll
            for (int an = 0; an < 4; an++) {
                int col = col0 + warp_col * 32 + an * 8 + (lid & 3) * 2 + (q & 1);
                size_t idx = (size_t)row * ldc + col;
                float v = acc[am][an][q];
                if (flags & FLAG_ATOMIC) {
                    atomicAdd(C + idx, v);
                } else {
                    if (bias) v += bias[col];
                    if (flags & FLAG_ACC) v += C[idx];
                    if (flags & FLAG_RELU) v = fmaxf(v, 0.f);
                    C[idx] = v;
                }
            }
        }
    }
}

// ================= pipelined fp16 pair MMA =================
#define PH_AHS   0
#define PH_ST0   8192
#define PH_STAGE 36864
#define PH_A     0
#define PH_W     18432
#define PH_RED   81920
#define PH_B2    82432
#define PH_W3    82944
#define PH_SMEM  83456

__global__ void __launch_bounds__(256, 2)
pair_mma_k(const float* __restrict__ Ah, const float* __restrict__ Ao,
           const __half* __restrict__ Wt, const float* __restrict__ b2,
           const float* __restrict__ w3, float* __restrict__ adjp)
{
    extern __shared__ char smem[];
    uint32_t sb = smem_u32(smem);
    const int tid = threadIdx.x;
    const int wid = tid >> 5, lid = tid & 31;
    const int col0 = blockIdx.x * 128;
    const int row0 = blockIdx.y * 128;
    const int h = row0 >> 8;
    const int nb = row0 & 255;
    const int warp_row = wid >> 2, warp_col = wid & 3;

    float* ahs = (float*)(smem + PH_AHS);
    if (tid < 128) {
        *(float*)(smem + PH_B2 + tid * 4) = b2[col0 + tid];
        *(float*)(smem + PH_W3 + tid * 4) = w3[col0 + tid];
        *(float*)(smem + PH_RED + tid * 4) = 0.f;
    }
    #pragma unroll
    for (int j = 0; j < 8; j++) ahs[tid + j * 256] = Ah[h * 2048 + tid + j * 256];
    __syncthreads();

    const int r = tid >> 1, kh = tid & 1;
    const float* aop = Ao + (size_t)(nb + r) * 2048 + kh * 32;
    const __half* whp = Wt + (size_t)(col0 + r) * 2048 + kh * 32;
    const uint32_t soff = (uint32_t)(r * 144 + kh * 64);

    float acc[4][4][4];
    #pragma unroll
    for (int i = 0; i < 4; i++)
        #pragma unroll
        for (int j = 0; j < 4; j++)
            #pragma unroll
            for (int q = 0; q < 4; q++) acc[i][j][q] = 0.f;

    float4 pa[8];

    // prologue: chunk 0
    {
        uint32_t stb = sb + PH_ST0;
        #pragma unroll
        for (int j = 0; j < 4; j++) cpasync16(stb + PH_W + soff + j * 16, whp + j * 8);
        CP_COMMIT();
        const float4* p = (const float4*)aop;
        #pragma unroll
        for (int j = 0; j < 8; j++) pa[j] = p[j];
        char* stc = smem + PH_ST0;
        const float* ah = ahs + kh * 32;
        #pragma unroll
        for (int j = 0; j < 8; j++) {
            float v0 = fmaxf(pa[j].x + ah[j * 4 + 0], 0.f);
            float v1 = fmaxf(pa[j].y + ah[j * 4 + 1], 0.f);
            float v2 = fmaxf(pa[j].z + ah[j * 4 + 2], 0.f);
            float v3 = fmaxf(pa[j].w + ah[j * 4 + 3], 0.f);
            __half2 p0 = __floats2half2_rn(v0, v1);
            __half2 p1 = __floats2half2_rn(v2, v3);
            *(uint2*)(stc + PH_A + soff + j * 8) = make_uint2(*(uint32_t*)&p0, *(uint32_t*)&p1);
        }
    }

    for (int c = 0; c < 32; c++) {
        const int cur = c & 1;
        CP_WAIT0();
        __syncthreads();
        if (c < 31) {
            uint32_t stb = sb + PH_ST0 + (cur ^ 1) * PH_STAGE;
            const int kn = (c + 1) * 64;
            #pragma unroll
            for (int j = 0; j < 4; j++) cpasync16(stb + PH_W + soff + j * 16, whp + kn + j * 8);
            CP_COMMIT();
            const float4* p = (const float4*)(aop + kn);
            #pragma unroll
            for (int j = 0; j < 8; j++) pa[j] = p[j];
        }
        uint32_t stb = sb + PH_ST0 + cur * PH_STAGE;
        pair_chunk_f16(stb + PH_A, stb + PH_W, acc, lid, warp_row, warp_col);
        if (c < 31) {
            char* stc = smem + PH_ST0 + (cur ^ 1) * PH_STAGE;
            const float* ah = ahs + (c + 1) * 64 + kh * 32;
            #pragma unroll
            for (int j = 0; j < 8; j++) {
                float v0 = fmaxf(pa[j].x + ah[j * 4 + 0], 0.f);
                float v1 = fmaxf(pa[j].y + ah[j * 4 + 1], 0.f);
                float v2 = fmaxf(pa[j].z + ah[j * 4 + 2], 0.f);
                float v3 = fmaxf(pa[j].w + ah[j * 4 + 3], 0.f);
                __half2 p0 = __floats2half2_rn(v0, v1);
                __half2 p1 = __floats2half2_rn(v2, v3);
                *(uint2*)(stc + PH_A + soff + j * 8) = make_uint2(*(uint32_t*)&p0, *(uint32_t*)&p1);
            }
        }
    }

    // fused epilogue: adjp[row] += relu(D + b2) . w3
    const float* b2s = (const float*)(smem + PH_B2);
    const float* w3s = (const float*)(smem + PH_W3);
    float* sred = (float*)(smem + PH_RED);
    #pragma unroll
    for (int am = 0; am < 4; am++) {
        float pl = 0.f, ph = 0.f;
        #pragma unroll
        for (int an = 0; an < 4; an++) {
            int cb = warp_col * 32 + an * 8 + 2 * (lid & 3);
            float w0 = w3s[cb], w1 = w3s[cb + 1];
            float bb0 = b2s[cb], bb1 = b2s[cb + 1];
            pl += fmaxf(acc[am][an][0] + bb0, 0.f) * w0 + fmaxf(acc[am][an][1] + bb1, 0.f) * w1;
            ph += fmaxf(acc[am][an][2] + bb0, 0.f) * w0 + fmaxf(acc[am][an][3] + bb1, 0.f) * w1;
        }
        pl += __shfl_xor_sync(0xffffffffu, pl, 1);
        pl += __shfl_xor_sync(0xffffffffu, pl, 2);
        ph += __shfl_xor_sync(0xffffffffu, ph, 1);
        ph += __shfl_xor_sync(0xffffffffu, ph, 2);
        if ((lid & 3) == 0) {
            int rloc = warp_row * 64 + am * 16 + (lid >> 2);
            atomicAdd(sred + rloc, pl);
            atomicAdd(sred + rloc + 8, ph);
        }
    }
    __syncthreads();
    if (tid < 128) atomicAdd(adjp + row0 + tid, sred[tid]);
}

// ---------------- adj = sigmoid(adjp + b_a3) ----------------
__global__ void adjfin_k(const float* __restrict__ adjp, const float* __restrict__ b3,
                         float* __restrict__ adj)
{
    int p = blockIdx.x * 256 + threadIdx.x;
    if (p < NPAIR) adj[p] = 1.f / (1.f + expf(-(adjp[p] + b3[0])));
}

// ---------------- agg_o[h,e] -> out[h*ols + e] ----------------
__global__ void aggo_k(const float* __restrict__ adj, const float* __restrict__ obj,
                       const float* __restrict__ nssa, float* __restrict__ out, int ols)
{
    int h = blockIdx.y;
    int e = blockIdx.x * 128 + threadIdx.x;
    __shared__ float sa[256];
    for (int i = threadIdx.x; i < 256; i += 128) sa[i] = adj[h * 256 + i];
    __syncthreads();
    float a1 = 0.f, a2 = 0.f;
    #pragma unroll 4
    for (int n = 0; n < 256; n++) {
        float a = sa[n];
        float om = obj[n * 1024 + e];
        float ns = nssa[n * 1024 + e];
        a1 += a * om;
        a2 += a * om * ns;
    }
    out[h * ols + e] = nssa[h * 1024 + e] * a1 - a2;
}

// ---------------- agg_h[n,e] -> out[n*ols + e] ----------------
__global__ void aggh_k(const float* __restrict__ adj, const float* __restrict__ hum,
                       const float* __restrict__ nssa, float* __restrict__ out, int ols)
{
    int n = blockIdx.y;
    int e = blockIdx.x * 128 + threadIdx.x;
    __shared__ float sa[64];
    if (threadIdx.x < 64) sa[threadIdx.x] = adj[threadIdx.x * 256 + n];
    __syncthreads();
    float a1 = 0.f, a2 = 0.f;
    #pragma unroll 4
    for (int h = 0; h < 64; h++) {
        float a = sa[h];
        float hm = hum[h * 1024 + e];
        float hs = nssa[h * 1024 + e];
        a1 += a * hm;
        a2 += a * hm * hs;
    }
    out[n * ols + e] = nssa[n * 1024 + e] * a1 - a2;
}

__global__ void detect_k(const unsigned char* __restrict__ cm)
{
    __shared__ int s_f, s_nz;
    if (threadIdx.x == 0) { s_f = 0; s_nz = 0; }
    __syncthreads();
    int lf = 0, lnz = 0;
    for (int i = threadIdx.x; i < 9360; i += blockDim.x) {
        unsigned char b = cm[i];
        int m4 = i & 3;
        if (m4 == 3 && b == 0x3F) lf = 1;
        if (m4 != 0 && b != 0) lnz = 1;
    }
    if (lf) atomicOr(&s_f, 1);
    if (lnz) atomicOr(&s_nz, 1);
    __syncthreads();
    if (threadIdx.x == 0) g_mask_mode = s_f ? 2 : (s_nz ? 0 : 1);
}

__device__ __forceinline__ float lisf(float x)
{
    return 8.3f / (1.f + expf(12.f - 10.f * x));
}

// ---------------- final gather: pair row = [hf[x] | of[y] | prior] ----------------
__global__ void out_k(const float* __restrict__ hf, const float* __restrict__ of,
                      const float* __restrict__ adj,
                      const float* __restrict__ scores, const int* __restrict__ labels,
                      const void* __restrict__ cmask, float* __restrict__ out)
{
    int p = blockIdx.x;
    int x = p / 255;
    int r = p % 255;
    int y = (r < x) ? r : r + 1;

    float scale = adj[x * 256 + y] * lisf(scores[x]) * lisf(scores[y]);
    int lab = labels[y];
    int mode = g_mask_mode;

    const float* hx = hf + x * 2048;
    const float* oy = of + y * 2048;
    float* o = out + (size_t)p * OUTC;

    for (int c = threadIdx.x; c < OUTC; c += blockDim.x) {
        float v;
        if (c < 2048)       v = hx[c];
        else if (c < 4096)  v = oy[c - 2048];
        else {
            int j = c - 4096;
            float m;
            if (mode == 0)      m = ((const unsigned char*)cmask)[lab * NCLS + j] ? 1.f : 0.f;
            else if (mode == 1) m = ((const int*)cmask)[lab * NCLS + j] ? 1.f : 0.f;
            else                m = ((const float*)cmask)[lab * NCLS + j];
            v = scale * m;
        }
        o[c] = v;
    }
}

// ---------------- host ----------------
static inline void launch_mma(const float* A, int lda,
                              const __nv_bfloat16* Bhi, const __nv_bfloat16* Blo,
                              const float* bias, float* C, int ldc,
                              int M, int N, int K, int nk, int flags)
{
    dim3 grid(N / 128, (M + 127) / 128, nk);
    mma_gemm_k<<<grid, 256, GM_SMEM>>>(A, lda, Bhi, Blo, bias, C, ldc, M, N, K, K / nk, flags);
}

extern "C" void kernel_launch(void* const* d_in, const int* in_sizes, int n_in,
                              void* d_out, int out_size)
{
    const float *box = 0, *nsp = 0, *scores = 0;
    const int *labels = 0;
    const void *cmask = 0;
    const float *W_bh1 = 0, *b_bh1 = 0, *W_bh2 = 0, *b_bh2 = 0, *W_sa = 0;
    const float *W_a1 = 0, *b_a1 = 0, *W_a2 = 0, *b_a2 = 0, *W_a3 = 0, *b_a3 = 0;
    const float *W_hm = 0, *b_hm = 0, *W_om = 0, *b_om = 0, *W_hu = 0, *W_ou = 0;

    int c256 = 0, c1k = 0, c1m = 0, c2m = 0;
    for (int i = 0; i < n_in; i++) {
        const void* p = d_in[i];
        switch (in_sizes[i]) {
            case 3211264:  box = (const float*)p; break;
            case 262144:   nsp = (const float*)p; break;
            case 256:      if (c256++ == 0) scores = (const float*)p; else labels = (const int*)p; break;
            case 9360:     cmask = p; break;
            case 12845056: W_bh1 = (const float*)p; break;
            case 1024:
                switch (c1k++) {
                    case 0: b_bh1 = (const float*)p; break;
                    case 1: b_bh2 = (const float*)p; break;
                    case 2: b_a2  = (const float*)p; break;
                    case 3: W_a3  = (const float*)p; break;
                    case 4: b_hm  = (const float*)p; break;
                    case 5: b_om  = (const float*)p; break;
                } break;
            case 1048576:
                switch (c1m++) {
                    case 0: W_bh2 = (const float*)p; break;
                    case 1: W_sa  = (const float*)p; break;
                    case 2: W_hm  = (const float*)p; break;
                    case 3: W_om  = (const float*)p; break;
                } break;
            case 8388608:  W_a1 = (const float*)p; break;
            case 2048:     b_a1 = (const float*)p; break;
            case 2097152:
                switch (c2m++) {
                    case 0: W_a2 = (const float*)p; break;
                    case 1: W_hu = (const float*)p; break;
                    case 2: W_ou = (const float*)p; break;
                } break;
            case 1:        b_a3 = (const float*)p; break;
            default: break;
        }
    }

    float *enc1, *nssa, *Ah, *Ao, *adjp, *adj, *obj, *hum, *hf, *hcat, *of, *ocat;
    cudaGetSymbolAddress((void**)&enc1, g_enc1);
    cudaGetSymbolAddress((void**)&nssa, g_nssa);
    cudaGetSymbolAddress((void**)&Ah,   g_Ah);
    cudaGetSymbolAddress((void**)&Ao,   g_Ao);
    cudaGetSymbolAddress((void**)&adjp, g_adjp);
    cudaGetSymbolAddress((void**)&adj,  g_adj);
    cudaGetSymbolAddress((void**)&obj,  g_obj);
    cudaGetSymbolAddress((void**)&hum,  g_hum);
    cudaGetSymbolAddress((void**)&hf,   g_hf);
    cudaGetSymbolAddress((void**)&hcat, g_hcat);
    cudaGetSymbolAddress((void**)&of,   g_of);
    cudaGetSymbolAddress((void**)&ocat, g_ocat);

    __nv_bfloat16 *bh1hi, *bh1lo, *bh2hi, *bh2lo, *sahi, *salo, *omhi, *omlo, *hmhi, *hmlo;
    __nv_bfloat16 *a1hi, *a1lo, *huhi, *hulo, *ouhi, *oulo;
    __half *a2h;
    cudaGetSymbolAddress((void**)&bh1hi, g_bh1hi);
    cudaGetSymbolAddress((void**)&bh1lo, g_bh1lo);
    cudaGetSymbolAddress((void**)&bh2hi, g_bh2hi);
    cudaGetSymbolAddress((void**)&bh2lo, g_bh2lo);
    cudaGetSymbolAddress((void**)&sahi,  g_sahi);
    cudaGetSymbolAddress((void**)&salo,  g_salo);
    cudaGetSymbolAddress((void**)&omhi,  g_omhi);
    cudaGetSymbolAddress((void**)&omlo,  g_omlo);
    cudaGetSymbolAddress((void**)&hmhi,  g_hmhi);
    cudaGetSymbolAddress((void**)&hmlo,  g_hmlo);
    cudaGetSymbolAddress((void**)&a1hi,  g_a1hi);
    cudaGetSymbolAddress((void**)&a1lo,  g_a1lo);
    cudaGetSymbolAddress((void**)&huhi,  g_huhi);
    cudaGetSymbolAddress((void**)&hulo,  g_hulo);
    cudaGetSymbolAddress((void**)&ouhi,  g_ouhi);
    cudaGetSymbolAddress((void**)&oulo,  g_oulo);
    cudaGetSymbolAddress((void**)&a2h,   g_a2h);

    cudaFuncSetAttribute(pair_mma_k, cudaFuncAttributeMaxDynamicSharedMemorySize, PH_SMEM);
    cudaFuncSetAttribute(mma_gemm_k, cudaFuncAttributeMaxDynamicSharedMemorySize, GM_SMEM);

    dim3 cb(32, 8);
    // ---- weight conversions ----
    convsplit_k<<<dim3(392, 32), cb>>>(W_bh1, bh1hi, bh1lo, 12544, 1024);
    convsplit_k<<<dim3(32, 32), cb>>>(W_bh2, bh2hi, bh2lo, 1024, 1024);
    convsplit_k<<<dim3(32, 32), cb>>>(W_sa,  sahi,  salo,  1024, 1024);
    convsplit_k<<<dim3(32, 32), cb>>>(W_om,  omhi,  omlo,  1024, 1024);
    convsplit_k<<<dim3(32, 32), cb>>>(W_hm,  hmhi,  hmlo,  1024, 1024);
    convsplit_k<<<dim3(64, 64), cb>>>(W_a1, a1hi, a1lo, 2048, 2048);
    convsplit_k<<<dim3(64, 64), cb>>>(W_a1 + (size_t)2048 * 2048,
                                      a1hi + (size_t)2048 * 2048,
                                      a1lo + (size_t)2048 * 2048, 2048, 2048);
    convsplit_k<<<dim3(64, 32), cb>>>(W_hu, huhi, hulo, 2048, 1024);
    convsplit_k<<<dim3(64, 32), cb>>>(W_ou, ouhi, oulo, 2048, 1024);
    convf16_k<<<dim3(64, 32), cb>>>(W_a2, a2h, 2048, 1024);

    // ---- encoder + buffer init ----
    zero_k<<<NOBJ * EDIM / 256, 256>>>(enc1, NOBJ * EDIM);
    launch_mma(box, 12544, bh1hi, bh1lo, 0, enc1, 1024, NOBJ, 1024, 12544, 7, FLAG_ATOMIC);
    bias_relu_k<<<NOBJ * EDIM / 256, 256>>>(enc1, b_bh1, NOBJ, 1024);
    launch_mma(enc1, 1024, bh2hi, bh2lo, b_bh2, of, 2048, NOBJ, 1024, 1024, 1, FLAG_RELU);
    launch_mma(nsp, 1024, sahi, salo, 0, nssa, 1024, NOBJ, 1024, 1024, 1, 0);

    copy2d_k<<<(NOBJ * 1024 + 255) / 256, 256>>>(of + 1024, 2048, (float*)nsp, 1024, NOBJ, 1024);
    copy2d_k<<<(NOBJ * 1024 + 255) / 256, 256>>>(ocat, 2048, of, 2048, NOBJ, 1024);
    copy2d_k<<<(NHUM * 1024 + 255) / 256, 256>>>(hf, 2048, of, 2048, NHUM, 1024);
    copy2d_k<<<(NHUM * 1024 + 255) / 256, 256>>>(hf + 1024, 2048, (float*)nsp, 1024, NHUM, 1024);
    copy2d_k<<<(NHUM * 1024 + 255) / 256, 256>>>(hcat, 2048, of, 2048, NHUM, 1024);

    for (int it = 0; it < 2; it++) {
        // A_h = hf @ W_a1[:2048] + b_a1 ; A_o = of @ W_a1[2048:]
        launch_mma(hf, 2048, a1hi, a1lo, b_a1, Ah, 2048, NHUM, 2048, 2048, 1, 0);
        launch_mma(of, 2048, a1hi + (size_t)2048 * 2048, a1lo + (size_t)2048 * 2048,
                   0, Ao, 2048, NOBJ, 2048, 2048, 1, 0);

        // adj pre-activation (fp16 fused pair GEMM)
        zero_k<<<NPAIR / 256, 256>>>(adjp, NPAIR);
        pair_mma_k<<<dim3(8, 128), 256, PH_SMEM>>>(Ah, Ao, a2h, b_a2, W_a3, adjp);
        adjfin_k<<<NPAIR / 256, 256>>>(adjp, b_a3, adj);

        // obj_msg, agg_o -> hcat right half
        launch_mma(of, 2048, omhi, omlo, b_om, obj, 1024, NOBJ, 1024, 1024, 1, FLAG_RELU);
        aggo_k<<<dim3(8, NHUM), 128>>>(adj, obj, nssa, hcat + 1024, 2048);

        // h_enc' = hcat @ W_hu -> hf left; refresh hcat left
        launch_mma(hcat, 2048, huhi, hulo, 0, hf, 2048, NHUM, 1024, 2048, 1, 0);
        copy2d_k<<<(NHUM * 1024 + 255) / 256, 256>>>(hcat, 2048, hf, 2048, NHUM, 1024);

        // hum_msg, agg_h -> ocat right half
        launch_mma(hf, 2048, hmhi, hmlo, b_hm, hum, 1024, NHUM, 1024, 1024, 1, FLAG_RELU);
        aggh_k<<<dim3(8, NOBJ), 128>>>(adj, hum, nssa, ocat + 1024, 2048);

        // enc' = ocat @ W_ou -> of left; refresh ocat left
        launch_mma(ocat, 2048, ouhi, oulo, 0, of, 2048, NOBJ, 1024, 2048, 1, 0);
        copy2d_k<<<(NOBJ * 1024 + 255) / 256, 256>>>(ocat, 2048, of, 2048, NOBJ, 1024);
    }

    // ---- final gather ----
    detect_k<<<1, 256>>>((const unsigned char*)cmask);
    out_k<<<NKEEP, 128>>>(hf, of, adj, scores, labels, cmask, (float*)d_out);
}